// round 10
// baseline (speedup 1.0000x reference)
#include <cuda_runtime.h>
#include <cuda_bf16.h>
#include <math.h>
#include <stdint.h>

// Problem constants
#define BB   8
#define LL   3072
#define DD   1024
#define TOPK 8
#define NF   1537          // LL/2 + 1

#define MTOT (BB * LL)     // 24576

// ---------------------------------------------------------------------------
// Static device scratch
// ---------------------------------------------------------------------------
__device__ float  g_Qt[(size_t)BB * DD * LL];     // q projected, [B][D][L]
__device__ float  g_Kt[(size_t)BB * DD * LL];     // k projected, [B][D][L]
__device__ float  g_V [(size_t)BB * LL * DD];     // v projected, [B][L][D]
__device__ float2 g_P[(size_t)BB * DD * NF];
__device__ float2 g_S[BB * NF];
__device__ float2 g_tw[LL];
__device__ float  g_w[BB * TOPK];
__device__ int    g_d[BB * TOPK];
// int8 two-limb quantized operands.
// A: 3 regions (Q,K,V inputs); region 0 reused by k_aggq for the out-GEMM.
__device__ __align__(16) signed char g_A1[(size_t)3 * MTOT * DD];
__device__ __align__(16) signed char g_A2[(size_t)3 * MTOT * DD];
__device__ __align__(16) signed char g_B1[(size_t)4 * DD * DD];  // Bq[n][k] = W[k][n]
__device__ __align__(16) signed char g_B2[(size_t)4 * DD * DD];
__device__ float g_sa[(size_t)3 * MTOT];    // per-m-row limb1 scales
__device__ float g_sb[4 * DD];              // per-n-row limb1 scales

// ---------------------------------------------------------------------------
// PTX helpers (all base-ISA; no 'a'-suffix features)
// ---------------------------------------------------------------------------
__device__ __forceinline__ uint32_t smem_u32(const void* p) {
    uint32_t a;
    asm("{ .reg .u64 t; cvta.to.shared.u64 t, %1; cvt.u32.u64 %0, t; }"
        : "=r"(a) : "l"(p));
    return a;
}
__device__ __forceinline__ void cp16(uint32_t s, const void* g) {
    asm volatile("cp.async.cg.shared.global [%0], [%1], 16;" :: "r"(s), "l"(g));
}
__device__ __forceinline__ void cp_commit() {
    asm volatile("cp.async.commit_group;");
}
__device__ __forceinline__ void ldmx4(uint32_t* r, uint32_t a) {
    asm("ldmatrix.sync.aligned.m8n8.x4.shared.b16 {%0,%1,%2,%3}, [%4];"
        : "=r"(r[0]), "=r"(r[1]), "=r"(r[2]), "=r"(r[3]) : "r"(a));
}
__device__ __forceinline__ void imma16832(int* d, const uint32_t* a,
                                          uint32_t b0, uint32_t b1) {
    asm("mma.sync.aligned.m16n8k32.row.col.s32.s8.s8.s32 "
        "{%0,%1,%2,%3}, {%4,%5,%6,%7}, {%8,%9}, {%0,%1,%2,%3};"
        : "+r"(d[0]), "+r"(d[1]), "+r"(d[2]), "+r"(d[3])
        : "r"(a[0]), "r"(a[1]), "r"(a[2]), "r"(a[3]), "r"(b0), "r"(b1));
}
// two-limb quantization: x ~= s*(q1 + q2/256), |resid| <= s/512 (rare clamp)
__device__ __forceinline__ void quant2(float x, float s, float inv,
                                       int& q1, int& q2) {
    float a1 = rintf(x * inv);
    float r  = x - a1 * s;
    float a2 = rintf(r * inv * 256.0f);
    a2 = fminf(fmaxf(a2, -127.0f), 127.0f);
    q1 = (int)a1; q2 = (int)a2;
}
__device__ __forceinline__ uint32_t pack4(int a, int b, int c, int d) {
    return (uint32_t)(a & 0xff) | ((uint32_t)(b & 0xff) << 8)
         | ((uint32_t)(c & 0xff) << 16) | ((uint32_t)(d & 0xff) << 24);
}

// ---------------------------------------------------------------------------
// Weight column-max: g_sb[z][n] = max_k |W[k][n]| / 127
// grid (DD/256, 4), 256 threads; coalesced over n.
// ---------------------------------------------------------------------------
__global__ __launch_bounds__(256) void k_wmax(
    const float* __restrict__ W0, const float* __restrict__ W1,
    const float* __restrict__ W2, const float* __restrict__ W3)
{
    int z = blockIdx.y;
    const float* W = (z == 0) ? W0 : (z == 1) ? W1 : (z == 2) ? W2 : W3;
    int n = blockIdx.x * 256 + threadIdx.x;
    float m0 = 0.f, m1 = 0.f, m2 = 0.f, m3 = 0.f;
#pragma unroll 4
    for (int k = 0; k < DD; k += 4) {
        m0 = fmaxf(m0, fabsf(W[(size_t)(k + 0) * DD + n]));
        m1 = fmaxf(m1, fabsf(W[(size_t)(k + 1) * DD + n]));
        m2 = fmaxf(m2, fabsf(W[(size_t)(k + 2) * DD + n]));
        m3 = fmaxf(m3, fabsf(W[(size_t)(k + 3) * DD + n]));
    }
    float mx = fmaxf(fmaxf(m0, m1), fmaxf(m2, m3));
    g_sb[z * DD + n] = fmaxf(mx, 1e-20f) / 127.0f;
}

// ---------------------------------------------------------------------------
// Weight transpose + int8 two-limb quantize: Bq[n][k] = quant(W[k][n])
// grid (32, 32, 4), block (32, 8)
// ---------------------------------------------------------------------------
__global__ void k_wquant(const float* __restrict__ W0, const float* __restrict__ W1,
                         const float* __restrict__ W2, const float* __restrict__ W3)
{
    __shared__ float t[32][33];
    int z = blockIdx.z;
    const float* W = (z == 0) ? W0 : (z == 1) ? W1 : (z == 2) ? W2 : W3;
    signed char* B1 = g_B1 + (size_t)z * DD * DD;
    signed char* B2 = g_B2 + (size_t)z * DD * DD;
    int n0 = blockIdx.x * 32, k0 = blockIdx.y * 32;
    int tx = threadIdx.x, ty = threadIdx.y;
#pragma unroll
    for (int j = 0; j < 32; j += 8)
        t[ty + j][tx] = W[(size_t)(k0 + ty + j) * DD + n0 + tx];
    __syncthreads();
#pragma unroll
    for (int j = 0; j < 32; j += 8) {
        int n = n0 + ty + j;
        float s = g_sb[z * DD + n];
        float inv = 1.0f / s;
        float x = t[tx][ty + j];         // = W[k0+tx][n]
        int q1, q2;
        quant2(x, s, inv, q1, q2);
        B1[(size_t)n * DD + k0 + tx] = (signed char)q1;
        B2[(size_t)n * DD + k0 + tx] = (signed char)q2;
    }
}

// ---------------------------------------------------------------------------
// Activation quantize for Q,K,V: one block per (row m, region).
// grid (MTOT, 3), 256 threads; per-row max then two-limb quantize.
// ---------------------------------------------------------------------------
__global__ __launch_bounds__(256) void k_aquant3(
    const float* __restrict__ X0, const float* __restrict__ X1,
    const float* __restrict__ X2)
{
    __shared__ float red[256];
    const int reg = blockIdx.y;
    const int m   = blockIdx.x;
    const float* X = ((reg == 0) ? X0 : (reg == 1) ? X1 : X2) + (size_t)m * DD;
    const int tid = threadIdx.x;

    float4 v = ((const float4*)X)[tid];
    float mx = fmaxf(fmaxf(fabsf(v.x), fabsf(v.y)), fmaxf(fabsf(v.z), fabsf(v.w)));
    red[tid] = mx;
    __syncthreads();
    for (int off = 128; off > 0; off >>= 1) {
        if (tid < off) red[tid] = fmaxf(red[tid], red[tid + off]);
        __syncthreads();
    }
    float rmax = fmaxf(red[0], 1e-20f);
    float s = rmax / 127.0f, inv = 127.0f / rmax;

    int q1[4], q2[4];
    quant2(v.x, s, inv, q1[0], q2[0]);
    quant2(v.y, s, inv, q1[1], q2[1]);
    quant2(v.z, s, inv, q1[2], q2[2]);
    quant2(v.w, s, inv, q1[3], q2[3]);
    size_t o = ((size_t)reg * MTOT + m) * (DD / 4) + tid;
    ((uint32_t*)g_A1)[o] = pack4(q1[0], q1[1], q1[2], q1[3]);
    ((uint32_t*)g_A2)[o] = pack4(q2[0], q2[1], q2[2], q2[3]);
    if (tid == 0) g_sa[(size_t)reg * MTOT + m] = s;
}

// ---------------------------------------------------------------------------
// int8 two-limb tensor-core GEMM:
//   C[m][n] = sa[m]*sb[n]*(A1.B1 + (A1.B2 + A2.B1)/256) + bias[n]
// (A2.B2/65536 dropped.) int32 accumulation over full K=1024 is exact.
// CTA tile 128x128, KC=64 (2 k32 steps), 512 threads = 16 warps (4m x 4n),
// warp tile 32x32, 3-stage cp.async. SMEM rows 128B = [limb1 64B | limb2 64B],
// XOR-swizzled in 16B segs. modes: 0/1 -> g_Qt/g_Kt transposed, 2 -> g_V,
// 3 -> Cext. zsel: derive (areg,widx,mode) from blockIdx.z.
// ---------------------------------------------------------------------------
#define KC 64
#define NCH (DD / KC)      // 16 chunks
#define OFF_B 16384
#define BUF_SZ 32768
#define NSTG 3

__global__ __launch_bounds__(512, 1)
void k_gemm(int areg, int widx, const float* __restrict__ bias0,
            const float* __restrict__ bias1, const float* __restrict__ bias2,
            float* __restrict__ Cext, int mode, int zsel)
{
    extern __shared__ __align__(16) char smem[];
    __shared__ float s_sa[128], s_sbb[128], s_bias[128];

    if (zsel) { areg = blockIdx.z; widx = blockIdx.z; mode = blockIdx.z; }
    const float* bias = (widx == 1) ? bias1 : (widx == 2) ? bias2 : bias0;

    const int tid  = threadIdx.x;
    const int wid  = tid >> 5;
    const int lane = tid & 31;
    const int n0 = blockIdx.x * 128;
    const int m0 = blockIdx.y * 128;
    const int mw = wid >> 2;      // 0..3
    const int nw = wid & 3;       // 0..3

    const signed char* A1 = g_A1 + (size_t)areg * MTOT * DD;
    const signed char* A2 = g_A2 + (size_t)areg * MTOT * DD;
    const signed char* B1 = g_B1 + (size_t)widx * DD * DD;
    const signed char* B2 = g_B2 + (size_t)widx * DD * DD;

    if (tid < 128) {
        s_sa[tid]   = g_sa[(size_t)areg * MTOT + m0 + tid];
        s_sbb[tid]  = g_sb[widx * DD + n0 + tid];
        s_bias[tid] = bias[n0 + tid];
    }

    const uint32_t sbase = smem_u32(smem);

    int accm[2][4][4], accx[2][4][4];
#pragma unroll
    for (int i = 0; i < 2; i++)
#pragma unroll
        for (int j = 0; j < 4; j++)
#pragma unroll
            for (int q = 0; q < 4; q++) { accm[i][j][q] = 0; accx[i][j][q] = 0; }

    // ---- async load of one KC=64 chunk into stage b ----
    // A: 128 rows x 8 segs (limb1 segs0-3, limb2 segs4-7) = 1024 lines; B same.
    auto load_chunk = [&](int c, int b) {
        uint32_t sb = sbase + b * BUF_SZ;
        const int k0 = c * KC;
#pragma unroll
        for (int u = 0; u < 2; u++) {
            int idx  = tid * 2 + u;          // [0, 1024)
            int row  = idx >> 3;
            int seg8 = idx & 7;
            int limb = seg8 >> 2;
            int seg  = seg8 & 3;
            uint32_t so = (uint32_t)(row * 128 + ((seg8 ^ (row & 7)) * 16));
            const signed char* gA = (limb ? A2 : A1)
                + (size_t)(m0 + row) * DD + k0 + seg * 16;
            cp16(sb + so, gA);
            const signed char* gB = (limb ? B2 : B1)
                + (size_t)(n0 + row) * DD + k0 + seg * 16;
            cp16(sb + OFF_B + so, gB);
        }
        cp_commit();
    };

    load_chunk(0, 0);
    load_chunk(1, 1);

    int bufc = 0;
    for (int c = 0; c < NCH; c++) {
        if (c + 2 < NCH) {
            int b2 = bufc + 2; if (b2 >= NSTG) b2 -= NSTG;
            load_chunk(c + 2, b2);
            asm volatile("cp.async.wait_group 2;");
        } else if (c + 1 < NCH) {
            asm volatile("cp.async.wait_group 1;");
        } else {
            asm volatile("cp.async.wait_group 0;");
        }
        __syncthreads();

        const uint32_t bufu = sbase + bufc * BUF_SZ;

#pragma unroll
        for (int ks = 0; ks < 2; ks++) {
            // A fragments (limb1 & limb2) for this warp's two m16 tiles
            uint32_t a1f[2][4], a2f[2][4];
            const int arow0 = mw * 32 + (lane & 7) + ((lane >> 3) & 1) * 8;
            const int sega  = ks * 2 + (lane >> 4);
#pragma unroll
            for (int mi = 0; mi < 2; mi++) {
                int row = arow0 + mi * 16;
                uint32_t ra = bufu + row * 128;
                ldmx4(a1f[mi], ra + ((sega       ^ (row & 7)) * 16));
                ldmx4(a2f[mi], ra + (((sega + 4) ^ (row & 7)) * 16));
            }
            // B fragments: warp n32 = 2 x (n16 per ldmx4), limb1 & limb2
            const int nrow0 = nw * 32 + (lane & 7) + (lane >> 4) * 8;
            const int segb  = ks * 2 + ((lane >> 3) & 1);
            uint32_t b1f[2][4], b2f[2][4];
#pragma unroll
            for (int g = 0; g < 2; g++) {
                int nrow = nrow0 + g * 16;
                uint32_t rb = bufu + OFF_B + nrow * 128;
                ldmx4(b1f[g], rb + ((segb       ^ (nrow & 7)) * 16));
                ldmx4(b2f[g], rb + (((segb + 4) ^ (nrow & 7)) * 16));
            }
            // main: A1.B1 -> 8 independent accumulators
#pragma unroll
            for (int g = 0; g < 2; g++)
#pragma unroll
                for (int h = 0; h < 2; h++)
#pragma unroll
                    for (int mi = 0; mi < 2; mi++)
                        imma16832(accm[mi][g * 2 + h], a1f[mi],
                                  b1f[g][h * 2], b1f[g][h * 2 + 1]);
            // cross: A1.B2 then A2.B1 (same 8 accs, reuse distance 8)
#pragma unroll
            for (int g = 0; g < 2; g++)
#pragma unroll
                for (int h = 0; h < 2; h++)
#pragma unroll
                    for (int mi = 0; mi < 2; mi++)
                        imma16832(accx[mi][g * 2 + h], a1f[mi],
                                  b2f[g][h * 2], b2f[g][h * 2 + 1]);
#pragma unroll
            for (int g = 0; g < 2; g++)
#pragma unroll
                for (int h = 0; h < 2; h++)
#pragma unroll
                    for (int mi = 0; mi < 2; mi++)
                        imma16832(accx[mi][g * 2 + h], a2f[mi],
                                  b1f[g][h * 2], b1f[g][h * 2 + 1]);
        }
        __syncthreads();
        bufc = (bufc + 1 == NSTG) ? 0 : bufc + 1;
    }

    // ---- Epilogue: dequantize + bias into smem (128 x 132 fp32) ----
    float* smemC = (float*)smem;
    const float inv256 = 1.0f / 256.0f;
#pragma unroll
    for (int mi = 0; mi < 2; mi++) {
        int r0 = mw * 32 + mi * 16 + (lane >> 2);
        float sa0 = s_sa[r0], sa1 = s_sa[r0 + 8];
#pragma unroll
        for (int nj = 0; nj < 4; nj++) {
            int cc = nw * 32 + nj * 8 + (lane & 3) * 2;
            float f0 = s_sbb[cc], f1 = s_sbb[cc + 1];
            float g0 = s_bias[cc], g1 = s_bias[cc + 1];
            int* M = accm[mi][nj];
            int* X = accx[mi][nj];
            smemC[r0 * 132 + cc]           = sa0 * f0 * ((float)M[0] + (float)X[0] * inv256) + g0;
            smemC[r0 * 132 + cc + 1]       = sa0 * f1 * ((float)M[1] + (float)X[1] * inv256) + g1;
            smemC[(r0 + 8) * 132 + cc]     = sa1 * f0 * ((float)M[2] + (float)X[2] * inv256) + g0;
            smemC[(r0 + 8) * 132 + cc + 1] = sa1 * f1 * ((float)M[3] + (float)X[3] * inv256) + g1;
        }
    }
    __syncthreads();

    if (mode <= 1) {
        float* dstT = (mode == 0) ? g_Qt : g_Kt;
        const int bB = m0 / LL;
        const int s0 = m0 - bB * LL;
#pragma unroll
        for (int i = 0; i < 8; i++) {
            int col = wid * 8 + i;
            float4 o;
            o.x = smemC[(lane * 4 + 0) * 132 + col];
            o.y = smemC[(lane * 4 + 1) * 132 + col];
            o.z = smemC[(lane * 4 + 2) * 132 + col];
            o.w = smemC[(lane * 4 + 3) * 132 + col];
            *(float4*)&dstT[((size_t)bB * DD + n0 + col) * LL + s0 + lane * 4] = o;
        }
    } else {
        float* dstN = (mode == 2) ? g_V : Cext;
        const int row = tid >> 2;
        const int cb  = (tid & 3) * 32;
        const size_t rb = (size_t)(m0 + row) * DD + n0 + cb;
#pragma unroll
        for (int i = 0; i < 8; i++)
            *(float4*)&dstN[rb + i * 4] = *(float4*)&smemC[row * 132 + cb + i * 4];
    }
}

// ---------------------------------------------------------------------------
// Twiddle init
// ---------------------------------------------------------------------------
__global__ void k_twiddle() {
    int j = blockIdx.x * blockDim.x + threadIdx.x;
    if (j < LL) {
        double a = -6.283185307179586476925286766559 * (double)j / (double)LL;
        g_tw[j] = make_float2((float)cos(a), (float)sin(a));
    }
}

// ---------------------------------------------------------------------------
// Mixed-radix (3 * 2^10) Stockham FFT in shared memory
// ---------------------------------------------------------------------------
__device__ __forceinline__ float2 cmul(float2 a, float2 b) {
    return make_float2(a.x * b.x - a.y * b.y, a.x * b.y + a.y * b.x);
}

template <int SGN>
__device__ float2* block_fft(float2* p0, float2* p1, int tid, int nt)
{
    {
        const float s0 = (SGN > 0) ? -0.86602540378443864676f
                                   :  0.86602540378443864676f;
        for (int p = tid; p < 1024; p += nt) {
            float2 a = p0[p], b = p0[p + 1024], c = p0[p + 2048];
            float ur = b.x + c.x, ui = b.y + c.y;
            float dr = b.x - c.x, di = b.y - c.y;
            float vr = a.x - 0.5f * ur, vi = a.y - 0.5f * ui;
            float wr = -s0 * di, wi = s0 * dr;
            float2 w1 = g_tw[p];       if (SGN < 0) w1.y = -w1.y;
            float2 w2 = g_tw[2 * p];   if (SGN < 0) w2.y = -w2.y;
            p1[3 * p]     = make_float2(a.x + ur, a.y + ui);
            p1[3 * p + 1] = cmul(make_float2(vr + wr, vi + wi), w1);
            p1[3 * p + 2] = cmul(make_float2(vr - wr, vi - wi), w2);
        }
    }
    __syncthreads();

    float2* px = p1;
    float2* py = p0;
    int n = 1024, s = 3;
    while (n > 1) {
        int m = n >> 1;
        int str = LL / n;
        for (int t = tid; t < 1536; t += nt) {
            int p = t / s;
            int q = t - p * s;
            float2 a = px[q + s * p];
            float2 b = px[q + s * (p + m)];
            float2 w = g_tw[p * str];  if (SGN < 0) w.y = -w.y;
            py[q + s * (2 * p)]     = make_float2(a.x + b.x, a.y + b.y);
            py[q + s * (2 * p + 1)] = cmul(make_float2(a.x - b.x, a.y - b.y), w);
        }
        __syncthreads();
        n = m; s <<= 1;
        float2* tp = px; px = py; py = tp;
    }
    return px;
}

// ---------------------------------------------------------------------------
// Forward FFT of q,k packed as z = q + i*k; write qhat * conj(khat)
// ---------------------------------------------------------------------------
__global__ __launch_bounds__(256) void k_fft()
{
    __shared__ __align__(16) float2 pool[2 * LL];
    float2* p0 = pool;
    float2* p1 = pool + LL;

    const int bc = blockIdx.x;
    const float* qr = g_Qt + (size_t)bc * LL;
    const float* kr = g_Kt + (size_t)bc * LL;
    const int tid = threadIdx.x;

    for (int i = tid; i < LL; i += 256) p0[i] = make_float2(qr[i], kr[i]);
    __syncthreads();

    float2* z = block_fft<1>(p0, p1, tid, 256);

    float2* P = g_P + (size_t)bc * NF;
    for (int f = tid; f < NF; f += 256) {
        float2 zf = z[f];
        int ridx = (f == 0) ? 0 : (LL - f);
        float2 zr = z[ridx];
        float qre = 0.5f * (zf.x + zr.x);
        float qim = 0.5f * (zf.y - zr.y);
        float dr = zf.x - zr.x;
        float di = zf.y + zr.y;
        float kre = 0.5f * di;
        float kim = -0.5f * dr;
        P[f] = make_float2(qre * kre + qim * kim, qim * kre - qre * kim);
    }
}

// ---------------------------------------------------------------------------
// Deterministic channel reduction: S[b,f] = sum_c P[b,c,f]
// ---------------------------------------------------------------------------
__global__ __launch_bounds__(256) void k_reduce()
{
    __shared__ float red[2][8][32];
    const int b    = blockIdx.y;
    const int lane = threadIdx.x & 31;
    const int cw   = threadIdx.x >> 5;
    const int f    = blockIdx.x * 32 + lane;

    float sr = 0.0f, si = 0.0f;
    if (f < NF) {
        for (int c = cw; c < DD; c += 8) {
            float2 v = g_P[((size_t)b * DD + c) * NF + f];
            sr += v.x; si += v.y;
        }
    }
    red[0][cw][lane] = sr;
    red[1][cw][lane] = si;
    __syncthreads();
    if (cw == 0 && f < NF) {
        float ar = 0.0f, ai = 0.0f;
#pragma unroll
        for (int w = 0; w < 8; w++) { ar += red[0][w][lane]; ai += red[1][w][lane]; }
        g_S[b * NF + f] = make_float2(ar, ai);
    }
}

// ---------------------------------------------------------------------------
// Per-batch inverse FFT -> mean_value, top-8 + softmax
// ---------------------------------------------------------------------------
__global__ __launch_bounds__(512) void k_ifft_topk()
{
    __shared__ __align__(16) float2 pool[2 * LL];
    float2* p0 = pool;
    float2* p1 = pool + LL;

    const int b = blockIdx.x;
    const int tid = threadIdx.x;
    const int nt = 512;

    for (int f = tid; f < LL; f += nt) {
        float2 v;
        if (f < NF) v = g_S[b * NF + f];
        else {
            float2 u = g_S[b * NF + (LL - f)];
            v = make_float2(u.x, -u.y);
        }
        p0[f] = v;
    }
    __syncthreads();

    float2* z = block_fft<-1>(p0, p1, tid, nt);

    float* meanArr = (float*)pool;
    float* redV    = meanArr + 3072;
    int*   redI    = (int*)(meanArr + 3584);

    const float scale = 1.0f / ((float)LL * (float)DD);
    for (int i = tid; i < LL; i += nt) meanArr[i] = z[i].x * scale;
    __syncthreads();

    float lw[TOPK];
    int   ld[TOPK];
    for (int k = 0; k < TOPK; k++) {
        float bv = -1e30f;
        int   bi = 0x7fffffff;
        for (int i = tid; i < LL; i += nt) {
            float v = meanArr[i];
            if (v > bv || (v == bv && i < bi)) { bv = v; bi = i; }
        }
        redV[tid] = bv; redI[tid] = bi;
        __syncthreads();
        for (int off = 256; off > 0; off >>= 1) {
            if (tid < off) {
                float v2 = redV[tid + off];
                int   i2 = redI[tid + off];
                if (v2 > redV[tid] || (v2 == redV[tid] && i2 < redI[tid])) {
                    redV[tid] = v2; redI[tid] = i2;
                }
            }
            __syncthreads();
        }
        if (tid == 0) {
            lw[k] = redV[0];
            ld[k] = redI[0];
            meanArr[redI[0]] = -1e30f;
        }
        __syncthreads();
    }

    if (tid == 0) {
        float mx = lw[0];
        for (int i = 1; i < TOPK; i++) mx = fmaxf(mx, lw[i]);
        float e[TOPK];
        float sum = 0.0f;
        for (int i = 0; i < TOPK; i++) { e[i] = expf(lw[i] - mx); sum += e[i]; }
        for (int i = 0; i < TOPK; i++) {
            g_w[b * TOPK + i] = e[i] / sum;
            g_d[b * TOPK + i] = ld[i];
        }
    }
}

// ---------------------------------------------------------------------------
// Time-delay aggregation fused with int8 two-limb quantization (region 0):
//   agg[c] = sum_i w[b,i] * V[b][(s+d_i)%L][c]
// grid (L, B), 256 threads (one row of 1024 per block).
// ---------------------------------------------------------------------------
__global__ __launch_bounds__(256) void k_aggq()
{
    __shared__ float ws[TOPK];
    __shared__ int   ds[TOPK];
    __shared__ float red[256];
    const int s = blockIdx.x;
    const int b = blockIdx.y;
    const int tid = threadIdx.x;
    if (tid < TOPK) { ws[tid] = g_w[b * TOPK + tid]; ds[tid] = g_d[b * TOPK + tid]; }
    __syncthreads();

    const float* Vb = g_V + (size_t)b * LL * DD;
    const int c = tid * 4;
    float4 acc = make_float4(0.f, 0.f, 0.f, 0.f);
#pragma unroll
    for (int i = 0; i < TOPK; i++) {
        int j = s + ds[i];
        if (j >= LL) j -= LL;
        float4 v = *(const float4*)(Vb + (size_t)j * DD + c);
        float w = ws[i];
        acc.x += w * v.x; acc.y += w * v.y; acc.z += w * v.z; acc.w += w * v.w;
    }

    float mx = fmaxf(fmaxf(fabsf(acc.x), fabsf(acc.y)),
                     fmaxf(fabsf(acc.z), fabsf(acc.w)));
    red[tid] = mx;
    __syncthreads();
    for (int off = 128; off > 0; off >>= 1) {
        if (tid < off) red[tid] = fmaxf(red[tid], red[tid + off]);
        __syncthreads();
    }
    float rmax = fmaxf(red[0], 1e-20f);
    float sc = rmax / 127.0f, inv = 127.0f / rmax;

    int q1[4], q2[4];
    quant2(acc.x, sc, inv, q1[0], q2[0]);
    quant2(acc.y, sc, inv, q1[1], q2[1]);
    quant2(acc.z, sc, inv, q1[2], q2[2]);
    quant2(acc.w, sc, inv, q1[3], q2[3]);
    const int m = b * LL + s;
    size_t o = (size_t)m * (DD / 4) + tid;
    ((uint32_t*)g_A1)[o] = pack4(q1[0], q1[1], q1[2], q1[3]);
    ((uint32_t*)g_A2)[o] = pack4(q2[0], q2[1], q2[2], q2[3]);
    if (tid == 0) g_sa[m] = sc;
}

// ---------------------------------------------------------------------------
// kernel_launch
// ---------------------------------------------------------------------------
extern "C" void kernel_launch(void* const* d_in, const int* in_sizes, int n_in,
                              void* d_out, int out_size)
{
    const float* queries = (const float*)d_in[0];
    const float* keys    = (const float*)d_in[1];
    const float* values  = (const float*)d_in[2];
    const float* Wq = (const float*)d_in[3];
    const float* bq = (const float*)d_in[4];
    const float* Wk = (const float*)d_in[5];
    const float* bk = (const float*)d_in[6];
    const float* Wv = (const float*)d_in[7];
    const float* bv = (const float*)d_in[8];
    const float* Wo = (const float*)d_in[9];
    const float* bo = (const float*)d_in[10];
    float* Out = (float*)d_out;

    (void)in_sizes; (void)n_in; (void)out_size;

    const int dynC = NSTG * BUF_SZ;   // 98304 (>= epilogue's 128*132*4 = 67584)
    cudaFuncSetAttribute(k_gemm, cudaFuncAttributeMaxDynamicSharedMemorySize, dynC);

    k_twiddle<<<(LL + 255) / 256, 256>>>();
    k_wmax<<<dim3(DD / 256, 4), 256>>>(Wq, Wk, Wv, Wo);
    k_wquant<<<dim3(32, 32, 4), dim3(32, 8)>>>(Wq, Wk, Wv, Wo);
    k_aquant3<<<dim3(MTOT, 3), 256>>>(queries, keys, values);

    // fused Q/K/V projection GEMMs (z selects operand set + output mode)
    k_gemm<<<dim3(DD / 128, MTOT / 128, 3), 512, dynC>>>(
        0, 0, bq, bk, bv, Out, 0, 1);

    k_fft<<<BB * DD, 256>>>();
    k_reduce<<<dim3((NF + 31) / 32, BB), 256>>>();
    k_ifft_topk<<<BB, 512>>>();
    k_aggq<<<dim3(LL, BB), 256>>>();

    k_gemm<<<dim3(DD / 128, MTOT / 128, 1), 512, dynC>>>(
        0, 3, bo, bo, bo, Out, 3, 0);
}

// round 11
// speedup vs baseline: 3.0266x; 3.0266x over previous
#include <cuda_runtime.h>
#include <cuda_fp16.h>
#include <math.h>
#include <stdint.h>

// Problem constants
#define BB   8
#define LL   3072
#define DD   1024
#define TOPK 8
#define NF   1537          // LL/2 + 1

#define MTOT (BB * LL)     // 24576

// ---------------------------------------------------------------------------
// Static device scratch
// ---------------------------------------------------------------------------
__device__ float  g_Qt[(size_t)BB * DD * LL];     // q projected, [B][D][L]
__device__ float  g_Kt[(size_t)BB * DD * LL];     // k projected, [B][D][L]
__device__ float  g_V [(size_t)BB * LL * DD];     // v projected, [B][L][D]
__device__ float2 g_P[(size_t)BB * DD * NF];
__device__ float2 g_S[BB * NF];
__device__ float2 g_tw[LL];
__device__ float  g_w[BB * TOPK];
__device__ int    g_d[BB * TOPK];
// fp16 two-limb A operands: 3 regions (Q,K,V); region 0 reused by k_agg.
// A = Ah + Al exactly to ~2^-22 rel; B single fp16 limb (error ~2^-11).
__device__ __align__(16) __half g_Ah[(size_t)3 * MTOT * DD];
__device__ __align__(16) __half g_Al[(size_t)3 * MTOT * DD];
__device__ __align__(16) __half g_Bh[(size_t)4 * DD * DD];   // Bh[n][k] = W[k][n]

// ---------------------------------------------------------------------------
// PTX helpers (all base-ISA; no 'a'-suffix features)
// ---------------------------------------------------------------------------
__device__ __forceinline__ uint32_t smem_u32(const void* p) {
    uint32_t a;
    asm("{ .reg .u64 t; cvta.to.shared.u64 t, %1; cvt.u32.u64 %0, t; }"
        : "=r"(a) : "l"(p));
    return a;
}
__device__ __forceinline__ void cp16(uint32_t s, const void* g) {
    asm volatile("cp.async.cg.shared.global [%0], [%1], 16;" :: "r"(s), "l"(g));
}
__device__ __forceinline__ void cp_commit() {
    asm volatile("cp.async.commit_group;");
}
// Not volatile — pure data ops; lets the scheduler hoist/interleave.
__device__ __forceinline__ void ldmx4(uint32_t* r, uint32_t a) {
    asm("ldmatrix.sync.aligned.m8n8.x4.shared.b16 {%0,%1,%2,%3}, [%4];"
        : "=r"(r[0]), "=r"(r[1]), "=r"(r[2]), "=r"(r[3]) : "r"(a));
}
__device__ __forceinline__ void mma16816(float* d, const uint32_t* a,
                                         uint32_t b0, uint32_t b1) {
    asm("mma.sync.aligned.m16n8k16.row.col.f32.f16.f16.f32 "
        "{%0,%1,%2,%3}, {%4,%5,%6,%7}, {%8,%9}, {%0,%1,%2,%3};"
        : "+f"(d[0]), "+f"(d[1]), "+f"(d[2]), "+f"(d[3])
        : "r"(a[0]), "r"(a[1]), "r"(a[2]), "r"(a[3]), "r"(b0), "r"(b1));
}
__device__ __forceinline__ uint32_t packh2(__half a, __half b) {
    __half2 t = __halves2half2(a, b);
    return *(uint32_t*)&t;
}

// ---------------------------------------------------------------------------
// Weight transpose + fp16 convert:  Bh[n][k] = fp16(W[k][n])
// grid (32, 32, 4), block (32, 8)
// ---------------------------------------------------------------------------
__global__ void k_wconv(const float* __restrict__ W0, const float* __restrict__ W1,
                        const float* __restrict__ W2, const float* __restrict__ W3)
{
    __shared__ float t[32][33];
    int z = blockIdx.z;
    const float* W = (z == 0) ? W0 : (z == 1) ? W1 : (z == 2) ? W2 : W3;
    __half* Bh = g_Bh + (size_t)z * DD * DD;
    int n0 = blockIdx.x * 32, k0 = blockIdx.y * 32;
    int tx = threadIdx.x, ty = threadIdx.y;
#pragma unroll
    for (int j = 0; j < 32; j += 8)
        t[ty + j][tx] = W[(size_t)(k0 + ty + j) * DD + n0 + tx];
    __syncthreads();
#pragma unroll
    for (int j = 0; j < 32; j += 8)
        Bh[(size_t)(n0 + ty + j) * DD + k0 + tx] = __float2half_rn(t[tx][ty + j]);
}

// ---------------------------------------------------------------------------
// A split for Q,K,V in one launch: fp32 -> fp16 hi/lo into region blockIdx.y
// grid (MTOT*DD/1024, 3), 256 threads, float4 per thread
// ---------------------------------------------------------------------------
__global__ __launch_bounds__(256) void k_asplit3(
    const float4* __restrict__ X0, const float4* __restrict__ X1,
    const float4* __restrict__ X2)
{
    const int reg = blockIdx.y;
    const float4* X = (reg == 0) ? X0 : (reg == 1) ? X1 : X2;
    size_t i = (size_t)blockIdx.x * 256 + threadIdx.x;
    float4 v = X[i];
    __half h0 = __float2half_rn(v.x), h1 = __float2half_rn(v.y);
    __half h2 = __float2half_rn(v.z), h3 = __float2half_rn(v.w);
    __half l0 = __float2half_rn(v.x - __half2float(h0));
    __half l1 = __float2half_rn(v.y - __half2float(h1));
    __half l2 = __float2half_rn(v.z - __half2float(h2));
    __half l3 = __float2half_rn(v.w - __half2float(h3));
    size_t o = (size_t)reg * (MTOT * DD / 4) + i;
    ((uint2*)g_Ah)[o] = make_uint2(packh2(h0, h1), packh2(h2, h3));
    ((uint2*)g_Al)[o] = make_uint2(packh2(l0, l1), packh2(l2, l3));
}

// ---------------------------------------------------------------------------
// Tensor-core GEMM (mma.sync fp16, 2-term limb split):
//   C[m][n] = sum_k (Ah+Al)[m][k] * Bh[n][k]  + bias[n]
// CTA tile 128x128, KC=64 (4 k16 steps), double-buffered cp.async,
// 8 warps (4m x 2n), warp tile 32x64, 16 distinct accumulators/warp.
// SMEM/stage 48KB: A1[16KB] A2[16KB] B[16KB]; 128B rows, 16B-seg XOR swizzle.
// zsel: derive (areg,widx,mode) from blockIdx.z (fused Q/K/V launch).
// modes: 0/1 -> transposed g_Qt/g_Kt, 2 -> g_V natural, 3 -> Cext natural.
// ---------------------------------------------------------------------------
#define KC 64
#define NCH (DD / KC)      // 16 chunks
#define OFF_A2 16384
#define OFF_B  32768
#define BUF_SZ 49152
#define NSTG 2

__global__ __launch_bounds__(256, 2)
void k_gemm(int areg, int widx, const float* __restrict__ bias0,
            const float* __restrict__ bias1, const float* __restrict__ bias2,
            float* __restrict__ Cext, int mode, int zsel)
{
    extern __shared__ __align__(16) char smem[];
    __shared__ float s_bias[128];

    if (zsel) { areg = blockIdx.z; widx = blockIdx.z; mode = blockIdx.z; }
    const float* bias = (widx == 1) ? bias1 : (widx == 2) ? bias2 : bias0;

    const int tid  = threadIdx.x;
    const int wid  = tid >> 5;
    const int lane = tid & 31;
    const int n0 = blockIdx.x * 128;
    const int m0 = blockIdx.y * 128;
    const int mw = wid >> 1;      // 0..3
    const int nw = wid & 1;       // 0..1

    const __half* Ah = g_Ah + (size_t)areg * MTOT * DD;
    const __half* Al = g_Al + (size_t)areg * MTOT * DD;
    const __half* Bh = g_Bh + (size_t)widx * DD * DD;

    if (tid < 128) s_bias[tid] = bias[n0 + tid];

    const uint32_t sbase = smem_u32(smem);

    float acc[2][8][4];
#pragma unroll
    for (int i = 0; i < 2; i++)
#pragma unroll
        for (int j = 0; j < 8; j++)
#pragma unroll
            for (int q = 0; q < 4; q++) acc[i][j][q] = 0.0f;

    // ---- async load of one KC=64 chunk into stage b ----
    // A limb1: 128 rows x 8 segs = 1024 lines; A limb2: 1024; B: 1024.
    auto load_chunk = [&](int c, int b) {
        uint32_t sb = sbase + b * BUF_SZ;
        const int k0 = c * KC;
#pragma unroll
        for (int u = 0; u < 4; u++) {
            int idx = tid * 4 + u;           // [0, 1024)
            int row = idx >> 3;
            int seg = idx & 7;
            uint32_t so = (uint32_t)(row * 128 + ((seg ^ (row & 7)) * 16));
            cp16(sb + so,          Ah + (size_t)(m0 + row) * DD + k0 + seg * 8);
            cp16(sb + OFF_A2 + so, Al + (size_t)(m0 + row) * DD + k0 + seg * 8);
            cp16(sb + OFF_B + so,  Bh + (size_t)(n0 + row) * DD + k0 + seg * 8);
        }
        cp_commit();
    };

    load_chunk(0, 0);

    for (int c = 0; c < NCH; c++) {
        if (c + 1 < NCH) {
            load_chunk(c + 1, (c + 1) & 1);
            asm volatile("cp.async.wait_group 1;");
        } else {
            asm volatile("cp.async.wait_group 0;");
        }
        __syncthreads();

        const uint32_t bufu = sbase + (c & 1) * BUF_SZ;

#pragma unroll
        for (int ks = 0; ks < 4; ks++) {
            // A fragments (limb1 & limb2) for this warp's two m16 tiles
            uint32_t a1f[2][4], a2f[2][4];
            const int arow0 = mw * 32 + (lane & 15);
            const int sega  = ks * 2 + (lane >> 4);
#pragma unroll
            for (int mi = 0; mi < 2; mi++) {
                int row = arow0 + mi * 16;
                uint32_t off = row * 128 + ((sega ^ (row & 7)) * 16);
                ldmx4(a1f[mi], bufu + off);
                ldmx4(a2f[mi], bufu + OFF_A2 + off);
            }
            // B fragments: 4 n16 groups (64 cols), single limb
            const int nrow0 = nw * 64 + ((lane >> 4) & 1) * 8 + (lane & 7);
            const int segb  = ks * 2 + ((lane >> 3) & 1);
            uint32_t bf[4][4];
#pragma unroll
            for (int gi = 0; gi < 4; gi++) {
                int nrow = nrow0 + gi * 16;
                ldmx4(bf[gi], bufu + OFF_B + nrow * 128 + ((segb ^ (nrow & 7)) * 16));
            }
            // term Ah*B : 16 distinct accumulators
#pragma unroll
            for (int gi = 0; gi < 4; gi++)
#pragma unroll
                for (int half = 0; half < 2; half++)
#pragma unroll
                    for (int mi = 0; mi < 2; mi++)
                        mma16816(acc[mi][gi * 2 + half], a1f[mi],
                                 bf[gi][half * 2], bf[gi][half * 2 + 1]);
            // term Al*B
#pragma unroll
            for (int gi = 0; gi < 4; gi++)
#pragma unroll
                for (int half = 0; half < 2; half++)
#pragma unroll
                    for (int mi = 0; mi < 2; mi++)
                        mma16816(acc[mi][gi * 2 + half], a2f[mi],
                                 bf[gi][half * 2], bf[gi][half * 2 + 1]);
        }
        __syncthreads();
    }

    // ---- Epilogue: stage C tile (128 x 132 fp32) in smem, write coalesced ----
    float* smemC = (float*)smem;
#pragma unroll
    for (int mi = 0; mi < 2; mi++) {
        int r0 = mw * 32 + mi * 16 + (lane >> 2);
#pragma unroll
        for (int ni = 0; ni < 8; ni++) {
            int col = nw * 64 + ni * 8 + (lane & 3) * 2;
            smemC[r0 * 132 + col]           = acc[mi][ni][0];
            smemC[r0 * 132 + col + 1]       = acc[mi][ni][1];
            smemC[(r0 + 8) * 132 + col]     = acc[mi][ni][2];
            smemC[(r0 + 8) * 132 + col + 1] = acc[mi][ni][3];
        }
    }
    __syncthreads();

    if (mode <= 1) {
        float* dstT = (mode == 0) ? g_Qt : g_Kt;
        const int bB = m0 / LL;
        const int s0 = m0 - bB * LL;
#pragma unroll
        for (int i = 0; i < 16; i++) {
            int col = wid * 16 + i;
            float bi = s_bias[col];
            float4 o;
            o.x = smemC[(lane * 4 + 0) * 132 + col] + bi;
            o.y = smemC[(lane * 4 + 1) * 132 + col] + bi;
            o.z = smemC[(lane * 4 + 2) * 132 + col] + bi;
            o.w = smemC[(lane * 4 + 3) * 132 + col] + bi;
            *(float4*)&dstT[((size_t)bB * DD + n0 + col) * LL + s0 + lane * 4] = o;
        }
    } else {
        float* dstN = (mode == 2) ? g_V : Cext;
        const int row = tid >> 1;
        const int cb  = (tid & 1) * 64;
        const size_t rb = (size_t)(m0 + row) * DD + n0 + cb;
#pragma unroll
        for (int i = 0; i < 16; i++) {
            float4 v = *(float4*)&smemC[row * 132 + cb + i * 4];
            v.x += s_bias[cb + i * 4 + 0];
            v.y += s_bias[cb + i * 4 + 1];
            v.z += s_bias[cb + i * 4 + 2];
            v.w += s_bias[cb + i * 4 + 3];
            *(float4*)&dstN[rb + i * 4] = v;
        }
    }
}

// ---------------------------------------------------------------------------
// Twiddle init
// ---------------------------------------------------------------------------
__global__ void k_twiddle() {
    int j = blockIdx.x * blockDim.x + threadIdx.x;
    if (j < LL) {
        double a = -6.283185307179586476925286766559 * (double)j / (double)LL;
        g_tw[j] = make_float2((float)cos(a), (float)sin(a));
    }
}

// ---------------------------------------------------------------------------
// Mixed-radix (3 * 2^10) Stockham FFT in shared memory
// ---------------------------------------------------------------------------
__device__ __forceinline__ float2 cmul(float2 a, float2 b) {
    return make_float2(a.x * b.x - a.y * b.y, a.x * b.y + a.y * b.x);
}

template <int SGN>
__device__ float2* block_fft(float2* p0, float2* p1, int tid, int nt)
{
    {
        const float s0 = (SGN > 0) ? -0.86602540378443864676f
                                   :  0.86602540378443864676f;
        for (int p = tid; p < 1024; p += nt) {
            float2 a = p0[p], b = p0[p + 1024], c = p0[p + 2048];
            float ur = b.x + c.x, ui = b.y + c.y;
            float dr = b.x - c.x, di = b.y - c.y;
            float vr = a.x - 0.5f * ur, vi = a.y - 0.5f * ui;
            float wr = -s0 * di, wi = s0 * dr;
            float2 w1 = g_tw[p];       if (SGN < 0) w1.y = -w1.y;
            float2 w2 = g_tw[2 * p];   if (SGN < 0) w2.y = -w2.y;
            p1[3 * p]     = make_float2(a.x + ur, a.y + ui);
            p1[3 * p + 1] = cmul(make_float2(vr + wr, vi + wi), w1);
            p1[3 * p + 2] = cmul(make_float2(vr - wr, vi - wi), w2);
        }
    }
    __syncthreads();

    float2* px = p1;
    float2* py = p0;
    int n = 1024, s = 3;
    while (n > 1) {
        int m = n >> 1;
        int str = LL / n;
        for (int t = tid; t < 1536; t += nt) {
            int p = t / s;
            int q = t - p * s;
            float2 a = px[q + s * p];
            float2 b = px[q + s * (p + m)];
            float2 w = g_tw[p * str];  if (SGN < 0) w.y = -w.y;
            py[q + s * (2 * p)]     = make_float2(a.x + b.x, a.y + b.y);
            py[q + s * (2 * p + 1)] = cmul(make_float2(a.x - b.x, a.y - b.y), w);
        }
        __syncthreads();
        n = m; s <<= 1;
        float2* tp = px; px = py; py = tp;
    }
    return px;
}

// ---------------------------------------------------------------------------
// Forward FFT of q,k packed as z = q + i*k; write qhat * conj(khat)
// ---------------------------------------------------------------------------
__global__ __launch_bounds__(256) void k_fft()
{
    __shared__ __align__(16) float2 pool[2 * LL];
    float2* p0 = pool;
    float2* p1 = pool + LL;

    const int bc = blockIdx.x;
    const float* qr = g_Qt + (size_t)bc * LL;
    const float* kr = g_Kt + (size_t)bc * LL;
    const int tid = threadIdx.x;

    for (int i = tid; i < LL; i += 256) p0[i] = make_float2(qr[i], kr[i]);
    __syncthreads();

    float2* z = block_fft<1>(p0, p1, tid, 256);

    float2* P = g_P + (size_t)bc * NF;
    for (int f = tid; f < NF; f += 256) {
        float2 zf = z[f];
        int ridx = (f == 0) ? 0 : (LL - f);
        float2 zr = z[ridx];
        float qre = 0.5f * (zf.x + zr.x);
        float qim = 0.5f * (zf.y - zr.y);
        float dr = zf.x - zr.x;
        float di = zf.y + zr.y;
        float kre = 0.5f * di;
        float kim = -0.5f * dr;
        P[f] = make_float2(qre * kre + qim * kim, qim * kre - qre * kim);
    }
}

// ---------------------------------------------------------------------------
// Deterministic channel reduction: S[b,f] = sum_c P[b,c,f]
// ---------------------------------------------------------------------------
__global__ __launch_bounds__(256) void k_reduce()
{
    __shared__ float red[2][8][32];
    const int b    = blockIdx.y;
    const int lane = threadIdx.x & 31;
    const int cw   = threadIdx.x >> 5;
    const int f    = blockIdx.x * 32 + lane;

    float sr = 0.0f, si = 0.0f;
    if (f < NF) {
        for (int c = cw; c < DD; c += 8) {
            float2 v = g_P[((size_t)b * DD + c) * NF + f];
            sr += v.x; si += v.y;
        }
    }
    red[0][cw][lane] = sr;
    red[1][cw][lane] = si;
    __syncthreads();
    if (cw == 0 && f < NF) {
        float ar = 0.0f, ai = 0.0f;
#pragma unroll
        for (int w = 0; w < 8; w++) { ar += red[0][w][lane]; ai += red[1][w][lane]; }
        g_S[b * NF + f] = make_float2(ar, ai);
    }
}

// ---------------------------------------------------------------------------
// Per-batch inverse FFT -> mean_value, top-8 + softmax
// ---------------------------------------------------------------------------
__global__ __launch_bounds__(512) void k_ifft_topk()
{
    __shared__ __align__(16) float2 pool[2 * LL];
    float2* p0 = pool;
    float2* p1 = pool + LL;

    const int b = blockIdx.x;
    const int tid = threadIdx.x;
    const int nt = 512;

    for (int f = tid; f < LL; f += nt) {
        float2 v;
        if (f < NF) v = g_S[b * NF + f];
        else {
            float2 u = g_S[b * NF + (LL - f)];
            v = make_float2(u.x, -u.y);
        }
        p0[f] = v;
    }
    __syncthreads();

    float2* z = block_fft<-1>(p0, p1, tid, nt);

    float* meanArr = (float*)pool;
    float* redV    = meanArr + 3072;
    int*   redI    = (int*)(meanArr + 3584);

    const float scale = 1.0f / ((float)LL * (float)DD);
    for (int i = tid; i < LL; i += nt) meanArr[i] = z[i].x * scale;
    __syncthreads();

    float lw[TOPK];
    int   ld[TOPK];
    for (int k = 0; k < TOPK; k++) {
        float bv = -1e30f;
        int   bi = 0x7fffffff;
        for (int i = tid; i < LL; i += nt) {
            float v = meanArr[i];
            if (v > bv || (v == bv && i < bi)) { bv = v; bi = i; }
        }
        redV[tid] = bv; redI[tid] = bi;
        __syncthreads();
        for (int off = 256; off > 0; off >>= 1) {
            if (tid < off) {
                float v2 = redV[tid + off];
                int   i2 = redI[tid + off];
                if (v2 > redV[tid] || (v2 == redV[tid] && i2 < redI[tid])) {
                    redV[tid] = v2; redI[tid] = i2;
                }
            }
            __syncthreads();
        }
        if (tid == 0) {
            lw[k] = redV[0];
            ld[k] = redI[0];
            meanArr[redI[0]] = -1e30f;
        }
        __syncthreads();
    }

    if (tid == 0) {
        float mx = lw[0];
        for (int i = 1; i < TOPK; i++) mx = fmaxf(mx, lw[i]);
        float e[TOPK];
        float sum = 0.0f;
        for (int i = 0; i < TOPK; i++) { e[i] = expf(lw[i] - mx); sum += e[i]; }
        for (int i = 0; i < TOPK; i++) {
            g_w[b * TOPK + i] = e[i] / sum;
            g_d[b * TOPK + i] = ld[i];
        }
    }
}

// ---------------------------------------------------------------------------
// Time-delay aggregation fused with the fp16 hi/lo split (writes region 0):
//   agg = sum_i w[b,i] * V[b][(s+d_i)%L][c]   ->  g_Ah/g_Al region 0
// grid (L, B), 256 threads.
// ---------------------------------------------------------------------------
__global__ __launch_bounds__(256) void k_agg()
{
    __shared__ float ws[TOPK];
    __shared__ int   ds[TOPK];
    const int s = blockIdx.x;
    const int b = blockIdx.y;
    const int tid = threadIdx.x;
    if (tid < TOPK) { ws[tid] = g_w[b * TOPK + tid]; ds[tid] = g_d[b * TOPK + tid]; }
    __syncthreads();

    const float* Vb = g_V + (size_t)b * LL * DD;
    const int c = tid * 4;
    float4 acc = make_float4(0.f, 0.f, 0.f, 0.f);
#pragma unroll
    for (int i = 0; i < TOPK; i++) {
        int j = s + ds[i];
        if (j >= LL) j -= LL;
        float4 v = *(const float4*)(Vb + (size_t)j * DD + c);
        float w = ws[i];
        acc.x += w * v.x; acc.y += w * v.y; acc.z += w * v.z; acc.w += w * v.w;
    }
    __half h0 = __float2half_rn(acc.x), h1 = __float2half_rn(acc.y);
    __half h2 = __float2half_rn(acc.z), h3 = __float2half_rn(acc.w);
    __half l0 = __float2half_rn(acc.x - __half2float(h0));
    __half l1 = __float2half_rn(acc.y - __half2float(h1));
    __half l2 = __float2half_rn(acc.z - __half2float(h2));
    __half l3 = __float2half_rn(acc.w - __half2float(h3));
    size_t idx = ((size_t)b * LL + s) * DD + c;
    *(uint2*)(g_Ah + idx) = make_uint2(packh2(h0, h1), packh2(h2, h3));
    *(uint2*)(g_Al + idx) = make_uint2(packh2(l0, l1), packh2(l2, l3));
}

// ---------------------------------------------------------------------------
// kernel_launch
// ---------------------------------------------------------------------------
extern "C" void kernel_launch(void* const* d_in, const int* in_sizes, int n_in,
                              void* d_out, int out_size)
{
    const float* queries = (const float*)d_in[0];
    const float* keys    = (const float*)d_in[1];
    const float* values  = (const float*)d_in[2];
    const float* Wq = (const float*)d_in[3];
    const float* bq = (const float*)d_in[4];
    const float* Wk = (const float*)d_in[5];
    const float* bk = (const float*)d_in[6];
    const float* Wv = (const float*)d_in[7];
    const float* bv = (const float*)d_in[8];
    const float* Wo = (const float*)d_in[9];
    const float* bo = (const float*)d_in[10];
    float* Out = (float*)d_out;

    (void)in_sizes; (void)n_in; (void)out_size;

    const int dynC = NSTG * BUF_SZ;   // 98304 (>= epilogue's 128*132*4 = 67584)
    cudaFuncSetAttribute(k_gemm, cudaFuncAttributeMaxDynamicSharedMemorySize, dynC);

    k_twiddle<<<(LL + 255) / 256, 256>>>();
    k_wconv<<<dim3(32, 32, 4), dim3(32, 8)>>>(Wq, Wk, Wv, Wo);

    const int nsplit = (int)((size_t)MTOT * DD / 1024);   // 24576 blocks
    k_asplit3<<<dim3(nsplit, 3), 256>>>((const float4*)queries,
                                        (const float4*)keys,
                                        (const float4*)values);

    // fused Q/K/V projection GEMMs (z selects operand set + output mode)
    k_gemm<<<dim3(DD / 128, MTOT / 128, 3), 256, dynC>>>(
        0, 0, bq, bk, bv, Out, 0, 1);

    k_fft<<<BB * DD, 256>>>();
    k_reduce<<<dim3((NF + 31) / 32, BB), 256>>>();
    k_ifft_topk<<<BB, 512>>>();
    k_agg<<<dim3(LL, BB), 256>>>();

    k_gemm<<<dim3(DD / 128, MTOT / 128, 1), 256, dynC>>>(
        0, 3, bo, bo, bo, Out, 3, 0);
}

// round 12
// speedup vs baseline: 3.4324x; 1.1341x over previous
#include <cuda_runtime.h>
#include <cuda_fp16.h>
#include <math.h>
#include <stdint.h>

// Problem constants
#define BB   8
#define LL   3072
#define DD   1024
#define TOPK 8
#define NF   1537          // LL/2 + 1

#define MTOT (BB * LL)     // 24576

// ---------------------------------------------------------------------------
// Static device scratch
// ---------------------------------------------------------------------------
__device__ float  g_Qt[(size_t)BB * DD * LL];     // q projected, [B][D][L]
__device__ float  g_Kt[(size_t)BB * DD * LL];     // k projected, [B][D][L]
__device__ float  g_V [(size_t)BB * LL * DD];     // v projected, [B][L][D]
__device__ float2 g_P[(size_t)BB * DD * NF];
__device__ float2 g_S[BB * NF];
__device__ float2 g_tw[LL];
__device__ float  g_w[BB * TOPK];
__device__ int    g_d[BB * TOPK];
// fp16 two-limb A operands: 3 regions (Q,K,V); region 0 reused by k_agg.
// Q/K use single limb (weights-path only, fp16 noise attenuated by softmax);
// V and the out-GEMM (region 0 rewrite) use both limbs.
__device__ __align__(16) __half g_Ah[(size_t)3 * MTOT * DD];
__device__ __align__(16) __half g_Al[(size_t)3 * MTOT * DD];
__device__ __align__(16) __half g_Bh[(size_t)4 * DD * DD];   // Bh[n][k] = W[k][n]

// ---------------------------------------------------------------------------
// PTX helpers (all base-ISA; no 'a'-suffix features)
// ---------------------------------------------------------------------------
__device__ __forceinline__ uint32_t smem_u32(const void* p) {
    uint32_t a;
    asm("{ .reg .u64 t; cvta.to.shared.u64 t, %1; cvt.u32.u64 %0, t; }"
        : "=r"(a) : "l"(p));
    return a;
}
__device__ __forceinline__ void cp16(uint32_t s, const void* g) {
    asm volatile("cp.async.cg.shared.global [%0], [%1], 16;" :: "r"(s), "l"(g));
}
__device__ __forceinline__ void cp_commit() {
    asm volatile("cp.async.commit_group;");
}
// Not volatile — pure data ops; lets the scheduler hoist/interleave.
__device__ __forceinline__ void ldmx4(uint32_t* r, uint32_t a) {
    asm("ldmatrix.sync.aligned.m8n8.x4.shared.b16 {%0,%1,%2,%3}, [%4];"
        : "=r"(r[0]), "=r"(r[1]), "=r"(r[2]), "=r"(r[3]) : "r"(a));
}
__device__ __forceinline__ void mma16816(float* d, const uint32_t* a,
                                         uint32_t b0, uint32_t b1) {
    asm("mma.sync.aligned.m16n8k16.row.col.f32.f16.f16.f32 "
        "{%0,%1,%2,%3}, {%4,%5,%6,%7}, {%8,%9}, {%0,%1,%2,%3};"
        : "+f"(d[0]), "+f"(d[1]), "+f"(d[2]), "+f"(d[3])
        : "r"(a[0]), "r"(a[1]), "r"(a[2]), "r"(a[3]), "r"(b0), "r"(b1));
}
__device__ __forceinline__ uint32_t packh2(__half a, __half b) {
    __half2 t = __halves2half2(a, b);
    return *(uint32_t*)&t;
}

// ---------------------------------------------------------------------------
// Weight transpose + fp16 convert:  Bh[n][k] = fp16(W[k][n])
// grid (32, 32, 4), block (32, 8)
// ---------------------------------------------------------------------------
__global__ void k_wconv(const float* __restrict__ W0, const float* __restrict__ W1,
                        const float* __restrict__ W2, const float* __restrict__ W3)
{
    __shared__ float t[32][33];
    int z = blockIdx.z;
    const float* W = (z == 0) ? W0 : (z == 1) ? W1 : (z == 2) ? W2 : W3;
    __half* Bh = g_Bh + (size_t)z * DD * DD;
    int n0 = blockIdx.x * 32, k0 = blockIdx.y * 32;
    int tx = threadIdx.x, ty = threadIdx.y;
#pragma unroll
    for (int j = 0; j < 32; j += 8)
        t[ty + j][tx] = W[(size_t)(k0 + ty + j) * DD + n0 + tx];
    __syncthreads();
#pragma unroll
    for (int j = 0; j < 32; j += 8)
        Bh[(size_t)(n0 + ty + j) * DD + k0 + tx] = __float2half_rn(t[tx][ty + j]);
}

// ---------------------------------------------------------------------------
// A convert for Q,K,V in one launch: fp32 -> fp16 into region blockIdx.y.
// Q/K (regions 0,1): hi limb only. V (region 2): hi + lo limbs.
// grid (MTOT*DD/1024, 3), 256 threads, float4 per thread
// ---------------------------------------------------------------------------
__global__ __launch_bounds__(256) void k_asplit3(
    const float4* __restrict__ X0, const float4* __restrict__ X1,
    const float4* __restrict__ X2)
{
    const int reg = blockIdx.y;
    const float4* X = (reg == 0) ? X0 : (reg == 1) ? X1 : X2;
    size_t i = (size_t)blockIdx.x * 256 + threadIdx.x;
    float4 v = X[i];
    __half h0 = __float2half_rn(v.x), h1 = __float2half_rn(v.y);
    __half h2 = __float2half_rn(v.z), h3 = __float2half_rn(v.w);
    size_t o = (size_t)reg * (MTOT * DD / 4) + i;
    ((uint2*)g_Ah)[o] = make_uint2(packh2(h0, h1), packh2(h2, h3));
    if (reg == 2) {
        __half l0 = __float2half_rn(v.x - __half2float(h0));
        __half l1 = __float2half_rn(v.y - __half2float(h1));
        __half l2 = __float2half_rn(v.z - __half2float(h2));
        __half l3 = __float2half_rn(v.w - __half2float(h3));
        ((uint2*)g_Al)[o] = make_uint2(packh2(l0, l1), packh2(l2, l3));
    }
}

// ---------------------------------------------------------------------------
// Tensor-core GEMM (mma.sync fp16, limb-split):
//   C[m][n] = sum_k (Ah [+ Al])[m][k] * Bh[n][k]  + bias[n]
// alimbs = 1 (Q/K projections) or 2 (V projection, out-GEMM).
// CTA tile 128x128, KC=64 (4 k16 steps), double-buffered cp.async,
// 8 warps (4m x 2n), warp tile 32x64, 16 distinct accumulators/warp.
// SMEM/stage 48KB: A1[16KB] A2[16KB] B[16KB]; 128B rows, 16B-seg XOR swizzle.
// zsel: derive (areg,widx,mode,alimbs) from blockIdx.z (fused Q/K/V launch).
// modes: 0/1 -> transposed g_Qt/g_Kt, 2 -> g_V natural, 3 -> Cext natural.
// ---------------------------------------------------------------------------
#define KC 64
#define NCH (DD / KC)      // 16 chunks
#define OFF_A2 16384
#define OFF_B  32768
#define BUF_SZ 49152
#define NSTG 2

__global__ __launch_bounds__(256, 2)
void k_gemm(int areg, int widx, const float* __restrict__ bias0,
            const float* __restrict__ bias1, const float* __restrict__ bias2,
            float* __restrict__ Cext, int mode, int zsel, int alimbs)
{
    extern __shared__ __align__(16) char smem[];
    __shared__ float s_bias[128];

    if (zsel) {
        areg = blockIdx.z; widx = blockIdx.z; mode = blockIdx.z;
        alimbs = (blockIdx.z == 2) ? 2 : 1;
    }
    const float* bias = (widx == 1) ? bias1 : (widx == 2) ? bias2 : bias0;

    const int tid  = threadIdx.x;
    const int wid  = tid >> 5;
    const int lane = tid & 31;
    const int n0 = blockIdx.x * 128;
    const int m0 = blockIdx.y * 128;
    const int mw = wid >> 1;      // 0..3
    const int nw = wid & 1;       // 0..1

    const __half* Ah = g_Ah + (size_t)areg * MTOT * DD;
    const __half* Al = g_Al + (size_t)areg * MTOT * DD;
    const __half* Bh = g_Bh + (size_t)widx * DD * DD;

    if (tid < 128) s_bias[tid] = bias[n0 + tid];

    const uint32_t sbase = smem_u32(smem);

    float acc[2][8][4];
#pragma unroll
    for (int i = 0; i < 2; i++)
#pragma unroll
        for (int j = 0; j < 8; j++)
#pragma unroll
            for (int q = 0; q < 4; q++) acc[i][j][q] = 0.0f;

    // ---- async load of one KC=64 chunk into stage b ----
    auto load_chunk = [&](int c, int b) {
        uint32_t sb = sbase + b * BUF_SZ;
        const int k0 = c * KC;
#pragma unroll
        for (int u = 0; u < 4; u++) {
            int idx = tid * 4 + u;           // [0, 1024)
            int row = idx >> 3;
            int seg = idx & 7;
            uint32_t so = (uint32_t)(row * 128 + ((seg ^ (row & 7)) * 16));
            cp16(sb + so,          Ah + (size_t)(m0 + row) * DD + k0 + seg * 8);
            if (alimbs == 2)
                cp16(sb + OFF_A2 + so, Al + (size_t)(m0 + row) * DD + k0 + seg * 8);
            cp16(sb + OFF_B + so,  Bh + (size_t)(n0 + row) * DD + k0 + seg * 8);
        }
        cp_commit();
    };

    load_chunk(0, 0);

    for (int c = 0; c < NCH; c++) {
        if (c + 1 < NCH) {
            load_chunk(c + 1, (c + 1) & 1);
            asm volatile("cp.async.wait_group 1;");
        } else {
            asm volatile("cp.async.wait_group 0;");
        }
        __syncthreads();

        const uint32_t bufu = sbase + (c & 1) * BUF_SZ;

#pragma unroll
        for (int ks = 0; ks < 4; ks++) {
            // A fragments for this warp's two m16 tiles
            uint32_t a1f[2][4], a2f[2][4];
            const int arow0 = mw * 32 + (lane & 15);
            const int sega  = ks * 2 + (lane >> 4);
#pragma unroll
            for (int mi = 0; mi < 2; mi++) {
                int row = arow0 + mi * 16;
                uint32_t off = row * 128 + ((sega ^ (row & 7)) * 16);
                ldmx4(a1f[mi], bufu + off);
                if (alimbs == 2) ldmx4(a2f[mi], bufu + OFF_A2 + off);
            }
            // B fragments: 4 n16 groups (64 cols), single limb
            const int nrow0 = nw * 64 + ((lane >> 4) & 1) * 8 + (lane & 7);
            const int segb  = ks * 2 + ((lane >> 3) & 1);
            uint32_t bf[4][4];
#pragma unroll
            for (int gi = 0; gi < 4; gi++) {
                int nrow = nrow0 + gi * 16;
                ldmx4(bf[gi], bufu + OFF_B + nrow * 128 + ((segb ^ (nrow & 7)) * 16));
            }
            // term Ah*B : 16 distinct accumulators
#pragma unroll
            for (int gi = 0; gi < 4; gi++)
#pragma unroll
                for (int half = 0; half < 2; half++)
#pragma unroll
                    for (int mi = 0; mi < 2; mi++)
                        mma16816(acc[mi][gi * 2 + half], a1f[mi],
                                 bf[gi][half * 2], bf[gi][half * 2 + 1]);
            // term Al*B (V projection and out-GEMM only)
            if (alimbs == 2) {
#pragma unroll
                for (int gi = 0; gi < 4; gi++)
#pragma unroll
                    for (int half = 0; half < 2; half++)
#pragma unroll
                        for (int mi = 0; mi < 2; mi++)
                            mma16816(acc[mi][gi * 2 + half], a2f[mi],
                                     bf[gi][half * 2], bf[gi][half * 2 + 1]);
            }
        }
        __syncthreads();
    }

    // ---- Epilogue: stage C tile (128 x 132 fp32) in smem, write coalesced ----
    float* smemC = (float*)smem;
#pragma unroll
    for (int mi = 0; mi < 2; mi++) {
        int r0 = mw * 32 + mi * 16 + (lane >> 2);
#pragma unroll
        for (int ni = 0; ni < 8; ni++) {
            int col = nw * 64 + ni * 8 + (lane & 3) * 2;
            smemC[r0 * 132 + col]           = acc[mi][ni][0];
            smemC[r0 * 132 + col + 1]       = acc[mi][ni][1];
            smemC[(r0 + 8) * 132 + col]     = acc[mi][ni][2];
            smemC[(r0 + 8) * 132 + col + 1] = acc[mi][ni][3];
        }
    }
    __syncthreads();

    if (mode <= 1) {
        float* dstT = (mode == 0) ? g_Qt : g_Kt;
        const int bB = m0 / LL;
        const int s0 = m0 - bB * LL;
#pragma unroll
        for (int i = 0; i < 16; i++) {
            int col = wid * 16 + i;
            float bi = s_bias[col];
            float4 o;
            o.x = smemC[(lane * 4 + 0) * 132 + col] + bi;
            o.y = smemC[(lane * 4 + 1) * 132 + col] + bi;
            o.z = smemC[(lane * 4 + 2) * 132 + col] + bi;
            o.w = smemC[(lane * 4 + 3) * 132 + col] + bi;
            *(float4*)&dstT[((size_t)bB * DD + n0 + col) * LL + s0 + lane * 4] = o;
        }
    } else {
        float* dstN = (mode == 2) ? g_V : Cext;
        const int row = tid >> 1;
        const int cb  = (tid & 1) * 64;
        const size_t rb = (size_t)(m0 + row) * DD + n0 + cb;
#pragma unroll
        for (int i = 0; i < 16; i++) {
            float4 v = *(float4*)&smemC[row * 132 + cb + i * 4];
            v.x += s_bias[cb + i * 4 + 0];
            v.y += s_bias[cb + i * 4 + 1];
            v.z += s_bias[cb + i * 4 + 2];
            v.w += s_bias[cb + i * 4 + 3];
            *(float4*)&dstN[rb + i * 4] = v;
        }
    }
}

// ---------------------------------------------------------------------------
// Twiddle init
// ---------------------------------------------------------------------------
__global__ void k_twiddle() {
    int j = blockIdx.x * blockDim.x + threadIdx.x;
    if (j < LL) {
        double a = -6.283185307179586476925286766559 * (double)j / (double)LL;
        g_tw[j] = make_float2((float)cos(a), (float)sin(a));
    }
}

// ---------------------------------------------------------------------------
// Mixed-radix (3 * 2^10) Stockham FFT in shared memory
// ---------------------------------------------------------------------------
__device__ __forceinline__ float2 cmul(float2 a, float2 b) {
    return make_float2(a.x * b.x - a.y * b.y, a.x * b.y + a.y * b.x);
}

template <int SGN>
__device__ float2* block_fft(float2* p0, float2* p1, int tid, int nt)
{
    {
        const float s0 = (SGN > 0) ? -0.86602540378443864676f
                                   :  0.86602540378443864676f;
        for (int p = tid; p < 1024; p += nt) {
            float2 a = p0[p], b = p0[p + 1024], c = p0[p + 2048];
            float ur = b.x + c.x, ui = b.y + c.y;
            float dr = b.x - c.x, di = b.y - c.y;
            float vr = a.x - 0.5f * ur, vi = a.y - 0.5f * ui;
            float wr = -s0 * di, wi = s0 * dr;
            float2 w1 = g_tw[p];       if (SGN < 0) w1.y = -w1.y;
            float2 w2 = g_tw[2 * p];   if (SGN < 0) w2.y = -w2.y;
            p1[3 * p]     = make_float2(a.x + ur, a.y + ui);
            p1[3 * p + 1] = cmul(make_float2(vr + wr, vi + wi), w1);
            p1[3 * p + 2] = cmul(make_float2(vr - wr, vi - wi), w2);
        }
    }
    __syncthreads();

    float2* px = p1;
    float2* py = p0;
    int n = 1024, s = 3;
    while (n > 1) {
        int m = n >> 1;
        int str = LL / n;
        for (int t = tid; t < 1536; t += nt) {
            int p = t / s;
            int q = t - p * s;
            float2 a = px[q + s * p];
            float2 b = px[q + s * (p + m)];
            float2 w = g_tw[p * str];  if (SGN < 0) w.y = -w.y;
            py[q + s * (2 * p)]     = make_float2(a.x + b.x, a.y + b.y);
            py[q + s * (2 * p + 1)] = cmul(make_float2(a.x - b.x, a.y - b.y), w);
        }
        __syncthreads();
        n = m; s <<= 1;
        float2* tp = px; px = py; py = tp;
    }
    return px;
}

// ---------------------------------------------------------------------------
// Forward FFT of q,k packed as z = q + i*k; write qhat * conj(khat)
// ---------------------------------------------------------------------------
__global__ __launch_bounds__(256) void k_fft()
{
    __shared__ __align__(16) float2 pool[2 * LL];
    float2* p0 = pool;
    float2* p1 = pool + LL;

    const int bc = blockIdx.x;
    const float* qr = g_Qt + (size_t)bc * LL;
    const float* kr = g_Kt + (size_t)bc * LL;
    const int tid = threadIdx.x;

    for (int i = tid; i < LL; i += 256) p0[i] = make_float2(qr[i], kr[i]);
    __syncthreads();

    float2* z = block_fft<1>(p0, p1, tid, 256);

    float2* P = g_P + (size_t)bc * NF;
    for (int f = tid; f < NF; f += 256) {
        float2 zf = z[f];
        int ridx = (f == 0) ? 0 : (LL - f);
        float2 zr = z[ridx];
        float qre = 0.5f * (zf.x + zr.x);
        float qim = 0.5f * (zf.y - zr.y);
        float dr = zf.x - zr.x;
        float di = zf.y + zr.y;
        float kre = 0.5f * di;
        float kim = -0.5f * dr;
        P[f] = make_float2(qre * kre + qim * kim, qim * kre - qre * kim);
    }
}

// ---------------------------------------------------------------------------
// Deterministic channel reduction: S[b,f] = sum_c P[b,c,f]
// ---------------------------------------------------------------------------
__global__ __launch_bounds__(256) void k_reduce()
{
    __shared__ float red[2][8][32];
    const int b    = blockIdx.y;
    const int lane = threadIdx.x & 31;
    const int cw   = threadIdx.x >> 5;
    const int f    = blockIdx.x * 32 + lane;

    float sr = 0.0f, si = 0.0f;
    if (f < NF) {
        for (int c = cw; c < DD; c += 8) {
            float2 v = g_P[((size_t)b * DD + c) * NF + f];
            sr += v.x; si += v.y;
        }
    }
    red[0][cw][lane] = sr;
    red[1][cw][lane] = si;
    __syncthreads();
    if (cw == 0 && f < NF) {
        float ar = 0.0f, ai = 0.0f;
#pragma unroll
        for (int w = 0; w < 8; w++) { ar += red[0][w][lane]; ai += red[1][w][lane]; }
        g_S[b * NF + f] = make_float2(ar, ai);
    }
}

// ---------------------------------------------------------------------------
// Per-batch inverse FFT -> mean_value, top-8 + softmax
// ---------------------------------------------------------------------------
__global__ __launch_bounds__(512) void k_ifft_topk()
{
    __shared__ __align__(16) float2 pool[2 * LL];
    float2* p0 = pool;
    float2* p1 = pool + LL;

    const int b = blockIdx.x;
    const int tid = threadIdx.x;
    const int nt = 512;

    for (int f = tid; f < LL; f += nt) {
        float2 v;
        if (f < NF) v = g_S[b * NF + f];
        else {
            float2 u = g_S[b * NF + (LL - f)];
            v = make_float2(u.x, -u.y);
        }
        p0[f] = v;
    }
    __syncthreads();

    float2* z = block_fft<-1>(p0, p1, tid, nt);

    float* meanArr = (float*)pool;
    float* redV    = meanArr + 3072;
    int*   redI    = (int*)(meanArr + 3584);

    const float scale = 1.0f / ((float)LL * (float)DD);
    for (int i = tid; i < LL; i += nt) meanArr[i] = z[i].x * scale;
    __syncthreads();

    float lw[TOPK];
    int   ld[TOPK];
    for (int k = 0; k < TOPK; k++) {
        float bv = -1e30f;
        int   bi = 0x7fffffff;
        for (int i = tid; i < LL; i += nt) {
            float v = meanArr[i];
            if (v > bv || (v == bv && i < bi)) { bv = v; bi = i; }
        }
        redV[tid] = bv; redI[tid] = bi;
        __syncthreads();
        for (int off = 256; off > 0; off >>= 1) {
            if (tid < off) {
                float v2 = redV[tid + off];
                int   i2 = redI[tid + off];
                if (v2 > redV[tid] || (v2 == redV[tid] && i2 < redI[tid])) {
                    redV[tid] = v2; redI[tid] = i2;
                }
            }
            __syncthreads();
        }
        if (tid == 0) {
            lw[k] = redV[0];
            ld[k] = redI[0];
            meanArr[redI[0]] = -1e30f;
        }
        __syncthreads();
    }

    if (tid == 0) {
        float mx = lw[0];
        for (int i = 1; i < TOPK; i++) mx = fmaxf(mx, lw[i]);
        float e[TOPK];
        float sum = 0.0f;
        for (int i = 0; i < TOPK; i++) { e[i] = expf(lw[i] - mx); sum += e[i]; }
        for (int i = 0; i < TOPK; i++) {
            g_w[b * TOPK + i] = e[i] / sum;
            g_d[b * TOPK + i] = ld[i];
        }
    }
}

// ---------------------------------------------------------------------------
// Time-delay aggregation fused with the fp16 hi/lo split (writes region 0):
//   agg = sum_i w[b,i] * V[b][(s+d_i)%L][c]   ->  g_Ah/g_Al region 0
// grid (L, B), 256 threads.
// ---------------------------------------------------------------------------
__global__ __launch_bounds__(256) void k_agg()
{
    __shared__ float ws[TOPK];
    __shared__ int   ds[TOPK];
    const int s = blockIdx.x;
    const int b = blockIdx.y;
    const int tid = threadIdx.x;
    if (tid < TOPK) { ws[tid] = g_w[b * TOPK + tid]; ds[tid] = g_d[b * TOPK + tid]; }
    __syncthreads();

    const float* Vb = g_V + (size_t)b * LL * DD;
    const int c = tid * 4;
    float4 acc = make_float4(0.f, 0.f, 0.f, 0.f);
#pragma unroll
    for (int i = 0; i < TOPK; i++) {
        int j = s + ds[i];
        if (j >= LL) j -= LL;
        float4 v = *(const float4*)(Vb + (size_t)j * DD + c);
        float w = ws[i];
        acc.x += w * v.x; acc.y += w * v.y; acc.z += w * v.z; acc.w += w * v.w;
    }
    __half h0 = __float2half_rn(acc.x), h1 = __float2half_rn(acc.y);
    __half h2 = __float2half_rn(acc.z), h3 = __float2half_rn(acc.w);
    __half l0 = __float2half_rn(acc.x - __half2float(h0));
    __half l1 = __float2half_rn(acc.y - __half2float(h1));
    __half l2 = __float2half_rn(acc.z - __half2float(h2));
    __half l3 = __float2half_rn(acc.w - __half2float(h3));
    size_t idx = ((size_t)b * LL + s) * DD + c;
    *(uint2*)(g_Ah + idx) = make_uint2(packh2(h0, h1), packh2(h2, h3));
    *(uint2*)(g_Al + idx) = make_uint2(packh2(l0, l1), packh2(l2, l3));
}

// ---------------------------------------------------------------------------
// kernel_launch
// ---------------------------------------------------------------------------
extern "C" void kernel_launch(void* const* d_in, const int* in_sizes, int n_in,
                              void* d_out, int out_size)
{
    const float* queries = (const float*)d_in[0];
    const float* keys    = (const float*)d_in[1];
    const float* values  = (const float*)d_in[2];
    const float* Wq = (const float*)d_in[3];
    const float* bq = (const float*)d_in[4];
    const float* Wk = (const float*)d_in[5];
    const float* bk = (const float*)d_in[6];
    const float* Wv = (const float*)d_in[7];
    const float* bv = (const float*)d_in[8];
    const float* Wo = (const float*)d_in[9];
    const float* bo = (const float*)d_in[10];
    float* Out = (float*)d_out;

    (void)in_sizes; (void)n_in; (void)out_size;

    const int dynC = NSTG * BUF_SZ;   // 98304 (>= epilogue's 128*132*4 = 67584)
    cudaFuncSetAttribute(k_gemm, cudaFuncAttributeMaxDynamicSharedMemorySize, dynC);

    k_twiddle<<<(LL + 255) / 256, 256>>>();
    k_wconv<<<dim3(32, 32, 4), dim3(32, 8)>>>(Wq, Wk, Wv, Wo);

    const int nsplit = (int)((size_t)MTOT * DD / 1024);   // 24576 blocks
    k_asplit3<<<dim3(nsplit, 3), 256>>>((const float4*)queries,
                                        (const float4*)keys,
                                        (const float4*)values);

    // fused Q/K/V projection GEMMs (z selects operand set + output mode;
    // Q/K single-limb A, V two-limb A)
    k_gemm<<<dim3(DD / 128, MTOT / 128, 3), 256, dynC>>>(
        0, 0, bq, bk, bv, Out, 0, 1, 2);

    k_fft<<<BB * DD, 256>>>();
    k_reduce<<<dim3((NF + 31) / 32, BB), 256>>>();
    k_ifft_topk<<<BB, 512>>>();
    k_agg<<<dim3(LL, BB), 256>>>();

    // output GEMM: two-limb A (direct path)
    k_gemm<<<dim3(DD / 128, MTOT / 128, 1), 256, dynC>>>(
        0, 3, bo, bo, bo, Out, 3, 0, 2);
}

// round 13
// speedup vs baseline: 3.6120x; 1.0523x over previous
#include <cuda_runtime.h>
#include <cuda_fp16.h>
#include <math.h>
#include <stdint.h>

// Problem constants
#define BB   8
#define LL   3072
#define DD   1024
#define TOPK 8
#define NF   1537          // LL/2 + 1

#define MTOT (BB * LL)     // 24576

// ---------------------------------------------------------------------------
// Static device scratch
// ---------------------------------------------------------------------------
__device__ float  g_Qt[(size_t)BB * DD * LL];     // q projected, [B][D][L]
__device__ float  g_Kt[(size_t)BB * DD * LL];     // k projected, [B][D][L]
__device__ float  g_V [(size_t)BB * LL * DD];     // Y = V@Wo + bo, [B][L][D]
__device__ float2 g_P[(size_t)BB * DD * NF];
__device__ float2 g_S[BB * NF];
__device__ float2 g_tw[LL];
__device__ float  g_w[BB * TOPK];
__device__ int    g_d[BB * TOPK];
// fp16 A operands: regions 0..2. asplit writes Q->0 (hi), K->1 (hi),
// V->2 (hi+lo). The V-projection GEMM epilogue writes V's fp16 limbs into
// region 0, which the Y-GEMM (V @ Wo) then consumes.
__device__ __align__(16) __half g_Ah[(size_t)3 * MTOT * DD];
__device__ __align__(16) __half g_Al[(size_t)3 * MTOT * DD];
__device__ __align__(16) __half g_Bh[(size_t)4 * DD * DD];   // Bh[n][k] = W[k][n]

// ---------------------------------------------------------------------------
// PTX helpers (all base-ISA; no 'a'-suffix features)
// ---------------------------------------------------------------------------
__device__ __forceinline__ uint32_t smem_u32(const void* p) {
    uint32_t a;
    asm("{ .reg .u64 t; cvta.to.shared.u64 t, %1; cvt.u32.u64 %0, t; }"
        : "=r"(a) : "l"(p));
    return a;
}
__device__ __forceinline__ void cp16(uint32_t s, const void* g) {
    asm volatile("cp.async.cg.shared.global [%0], [%1], 16;" :: "r"(s), "l"(g));
}
__device__ __forceinline__ void cp_commit() {
    asm volatile("cp.async.commit_group;");
}
// Not volatile — pure data ops; lets the scheduler hoist/interleave.
__device__ __forceinline__ void ldmx4(uint32_t* r, uint32_t a) {
    asm("ldmatrix.sync.aligned.m8n8.x4.shared.b16 {%0,%1,%2,%3}, [%4];"
        : "=r"(r[0]), "=r"(r[1]), "=r"(r[2]), "=r"(r[3]) : "r"(a));
}
__device__ __forceinline__ void mma16816(float* d, const uint32_t* a,
                                         uint32_t b0, uint32_t b1) {
    asm("mma.sync.aligned.m16n8k16.row.col.f32.f16.f16.f32 "
        "{%0,%1,%2,%3}, {%4,%5,%6,%7}, {%8,%9}, {%0,%1,%2,%3};"
        : "+f"(d[0]), "+f"(d[1]), "+f"(d[2]), "+f"(d[3])
        : "r"(a[0]), "r"(a[1]), "r"(a[2]), "r"(a[3]), "r"(b0), "r"(b1));
}
__device__ __forceinline__ uint32_t packh2(__half a, __half b) {
    __half2 t = __halves2half2(a, b);
    return *(uint32_t*)&t;
}

// ---------------------------------------------------------------------------
// Weight transpose + fp16 convert:  Bh[n][k] = fp16(W[k][n])
// grid (32, 32, 4), block (32, 8)
// ---------------------------------------------------------------------------
__global__ void k_wconv(const float* __restrict__ W0, const float* __restrict__ W1,
                        const float* __restrict__ W2, const float* __restrict__ W3)
{
    __shared__ float t[32][33];
    int z = blockIdx.z;
    const float* W = (z == 0) ? W0 : (z == 1) ? W1 : (z == 2) ? W2 : W3;
    __half* Bh = g_Bh + (size_t)z * DD * DD;
    int n0 = blockIdx.x * 32, k0 = blockIdx.y * 32;
    int tx = threadIdx.x, ty = threadIdx.y;
#pragma unroll
    for (int j = 0; j < 32; j += 8)
        t[ty + j][tx] = W[(size_t)(k0 + ty + j) * DD + n0 + tx];
    __syncthreads();
#pragma unroll
    for (int j = 0; j < 32; j += 8)
        Bh[(size_t)(n0 + ty + j) * DD + k0 + tx] = __float2half_rn(t[tx][ty + j]);
}

// ---------------------------------------------------------------------------
// A convert for Q,K,V in one launch: fp32 -> fp16 into region blockIdx.y.
// Q/K (regions 0,1): hi limb only. V (region 2): hi + lo limbs.
// ---------------------------------------------------------------------------
__global__ __launch_bounds__(256) void k_asplit3(
    const float4* __restrict__ X0, const float4* __restrict__ X1,
    const float4* __restrict__ X2)
{
    const int reg = blockIdx.y;
    const float4* X = (reg == 0) ? X0 : (reg == 1) ? X1 : X2;
    size_t i = (size_t)blockIdx.x * 256 + threadIdx.x;
    float4 v = X[i];
    __half h0 = __float2half_rn(v.x), h1 = __float2half_rn(v.y);
    __half h2 = __float2half_rn(v.z), h3 = __float2half_rn(v.w);
    size_t o = (size_t)reg * (MTOT * DD / 4) + i;
    ((uint2*)g_Ah)[o] = make_uint2(packh2(h0, h1), packh2(h2, h3));
    if (reg == 2) {
        __half l0 = __float2half_rn(v.x - __half2float(h0));
        __half l1 = __float2half_rn(v.y - __half2float(h1));
        __half l2 = __float2half_rn(v.z - __half2float(h2));
        __half l3 = __float2half_rn(v.w - __half2float(h3));
        ((uint2*)g_Al)[o] = make_uint2(packh2(l0, l1), packh2(l2, l3));
    }
}

// ---------------------------------------------------------------------------
// Tensor-core GEMM (mma.sync fp16, limb-split):
//   C[m][n] = sum_k (Ah [+ Al])[m][k] * Bh[n][k]  + bias[n]
// alimbs = 1 (Q/K projections) or 2 (V projection, Y-GEMM).
// CTA tile 128x128, KC=64 (4 k16 steps), double-buffered cp.async,
// 8 warps (4m x 2n), warp tile 32x64, 16 distinct accumulators/warp.
// SMEM/stage 48KB: A1[16KB] A2[16KB] B[16KB]; 128B rows, 16B-seg XOR swizzle.
// zsel: derive (areg,widx,mode,alimbs) from blockIdx.z (fused Q/K/V launch).
// modes: 0/1 -> transposed g_Qt/g_Kt; 2 -> fp16 limbs into region 0 (V-proj);
//        3 -> float natural into g_V (Y = V@Wo + bo).
// ---------------------------------------------------------------------------
#define KC 64
#define NCH (DD / KC)      // 16 chunks
#define OFF_A2 16384
#define OFF_B  32768
#define BUF_SZ 49152
#define NSTG 2

__global__ __launch_bounds__(256, 2)
void k_gemm(int areg, int widx, const float* __restrict__ bias0,
            const float* __restrict__ bias1, const float* __restrict__ bias2,
            float* __restrict__ Cext, int mode, int zsel, int alimbs)
{
    extern __shared__ __align__(16) char smem[];
    __shared__ float s_bias[128];

    if (zsel) {
        areg = blockIdx.z; widx = blockIdx.z; mode = blockIdx.z;
        alimbs = (blockIdx.z == 2) ? 2 : 1;
    }
    const float* bias = (widx == 1) ? bias1 : (widx == 2) ? bias2 : bias0;

    const int tid  = threadIdx.x;
    const int wid  = tid >> 5;
    const int lane = tid & 31;
    const int n0 = blockIdx.x * 128;
    const int m0 = blockIdx.y * 128;
    const int mw = wid >> 1;      // 0..3
    const int nw = wid & 1;       // 0..1

    const __half* Ah = g_Ah + (size_t)areg * MTOT * DD;
    const __half* Al = g_Al + (size_t)areg * MTOT * DD;
    const __half* Bh = g_Bh + (size_t)widx * DD * DD;

    if (tid < 128) s_bias[tid] = bias[n0 + tid];

    const uint32_t sbase = smem_u32(smem);

    float acc[2][8][4];
#pragma unroll
    for (int i = 0; i < 2; i++)
#pragma unroll
        for (int j = 0; j < 8; j++)
#pragma unroll
            for (int q = 0; q < 4; q++) acc[i][j][q] = 0.0f;

    // ---- async load of one KC=64 chunk into stage b ----
    auto load_chunk = [&](int c, int b) {
        uint32_t sb = sbase + b * BUF_SZ;
        const int k0 = c * KC;
#pragma unroll
        for (int u = 0; u < 4; u++) {
            int idx = tid * 4 + u;           // [0, 1024)
            int row = idx >> 3;
            int seg = idx & 7;
            uint32_t so = (uint32_t)(row * 128 + ((seg ^ (row & 7)) * 16));
            cp16(sb + so,          Ah + (size_t)(m0 + row) * DD + k0 + seg * 8);
            if (alimbs == 2)
                cp16(sb + OFF_A2 + so, Al + (size_t)(m0 + row) * DD + k0 + seg * 8);
            cp16(sb + OFF_B + so,  Bh + (size_t)(n0 + row) * DD + k0 + seg * 8);
        }
        cp_commit();
    };

    load_chunk(0, 0);

    for (int c = 0; c < NCH; c++) {
        if (c + 1 < NCH) {
            load_chunk(c + 1, (c + 1) & 1);
            asm volatile("cp.async.wait_group 1;");
        } else {
            asm volatile("cp.async.wait_group 0;");
        }
        __syncthreads();

        const uint32_t bufu = sbase + (c & 1) * BUF_SZ;

#pragma unroll
        for (int ks = 0; ks < 4; ks++) {
            uint32_t a1f[2][4], a2f[2][4];
            const int arow0 = mw * 32 + (lane & 15);
            const int sega  = ks * 2 + (lane >> 4);
#pragma unroll
            for (int mi = 0; mi < 2; mi++) {
                int row = arow0 + mi * 16;
                uint32_t off = row * 128 + ((sega ^ (row & 7)) * 16);
                ldmx4(a1f[mi], bufu + off);
                if (alimbs == 2) ldmx4(a2f[mi], bufu + OFF_A2 + off);
            }
            const int nrow0 = nw * 64 + ((lane >> 4) & 1) * 8 + (lane & 7);
            const int segb  = ks * 2 + ((lane >> 3) & 1);
            uint32_t bf[4][4];
#pragma unroll
            for (int gi = 0; gi < 4; gi++) {
                int nrow = nrow0 + gi * 16;
                ldmx4(bf[gi], bufu + OFF_B + nrow * 128 + ((segb ^ (nrow & 7)) * 16));
            }
#pragma unroll
            for (int gi = 0; gi < 4; gi++)
#pragma unroll
                for (int half = 0; half < 2; half++)
#pragma unroll
                    for (int mi = 0; mi < 2; mi++)
                        mma16816(acc[mi][gi * 2 + half], a1f[mi],
                                 bf[gi][half * 2], bf[gi][half * 2 + 1]);
            if (alimbs == 2) {
#pragma unroll
                for (int gi = 0; gi < 4; gi++)
#pragma unroll
                    for (int half = 0; half < 2; half++)
#pragma unroll
                        for (int mi = 0; mi < 2; mi++)
                            mma16816(acc[mi][gi * 2 + half], a2f[mi],
                                     bf[gi][half * 2], bf[gi][half * 2 + 1]);
            }
        }
        __syncthreads();
        bufc_dummy: ;
    }

    // ---- Epilogue: stage C tile (128 x 132 fp32) in smem, write coalesced ----
    float* smemC = (float*)smem;
#pragma unroll
    for (int mi = 0; mi < 2; mi++) {
        int r0 = mw * 32 + mi * 16 + (lane >> 2);
#pragma unroll
        for (int ni = 0; ni < 8; ni++) {
            int col = nw * 64 + ni * 8 + (lane & 3) * 2;
            smemC[r0 * 132 + col]           = acc[mi][ni][0];
            smemC[r0 * 132 + col + 1]       = acc[mi][ni][1];
            smemC[(r0 + 8) * 132 + col]     = acc[mi][ni][2];
            smemC[(r0 + 8) * 132 + col + 1] = acc[mi][ni][3];
        }
    }
    __syncthreads();

    if (mode <= 1) {
        float* dstT = (mode == 0) ? g_Qt : g_Kt;
        const int bB = m0 / LL;
        const int s0 = m0 - bB * LL;
#pragma unroll
        for (int i = 0; i < 16; i++) {
            int col = wid * 16 + i;
            float bi = s_bias[col];
            float4 o;
            o.x = smemC[(lane * 4 + 0) * 132 + col] + bi;
            o.y = smemC[(lane * 4 + 1) * 132 + col] + bi;
            o.z = smemC[(lane * 4 + 2) * 132 + col] + bi;
            o.w = smemC[(lane * 4 + 3) * 132 + col] + bi;
            *(float4*)&dstT[((size_t)bB * DD + n0 + col) * LL + s0 + lane * 4] = o;
        }
    } else if (mode == 2) {
        // V projection: write fp16 hi/lo limbs of (C + bias) into region 0
        const int row = tid >> 1;
        const int cb  = (tid & 1) * 64;
        const size_t rb = (size_t)(m0 + row) * DD + n0 + cb;
#pragma unroll
        for (int i = 0; i < 16; i++) {
            float4 v = *(float4*)&smemC[row * 132 + cb + i * 4];
            v.x += s_bias[cb + i * 4 + 0];
            v.y += s_bias[cb + i * 4 + 1];
            v.z += s_bias[cb + i * 4 + 2];
            v.w += s_bias[cb + i * 4 + 3];
            __half h0 = __float2half_rn(v.x), h1 = __float2half_rn(v.y);
            __half h2 = __float2half_rn(v.z), h3 = __float2half_rn(v.w);
            __half l0 = __float2half_rn(v.x - __half2float(h0));
            __half l1 = __float2half_rn(v.y - __half2float(h1));
            __half l2 = __float2half_rn(v.z - __half2float(h2));
            __half l3 = __float2half_rn(v.w - __half2float(h3));
            *(uint2*)(g_Ah + rb + i * 4) = make_uint2(packh2(h0, h1), packh2(h2, h3));
            *(uint2*)(g_Al + rb + i * 4) = make_uint2(packh2(l0, l1), packh2(l2, l3));
        }
    } else {
        // Y = V @ Wo + bo, float natural layout into g_V
        const int row = tid >> 1;
        const int cb  = (tid & 1) * 64;
        const size_t rb = (size_t)(m0 + row) * DD + n0 + cb;
#pragma unroll
        for (int i = 0; i < 16; i++) {
            float4 v = *(float4*)&smemC[row * 132 + cb + i * 4];
            v.x += s_bias[cb + i * 4 + 0];
            v.y += s_bias[cb + i * 4 + 1];
            v.z += s_bias[cb + i * 4 + 2];
            v.w += s_bias[cb + i * 4 + 3];
            *(float4*)&g_V[rb + i * 4] = v;
        }
    }
    (void)Cext;
}

// ---------------------------------------------------------------------------
// Twiddle init
// ---------------------------------------------------------------------------
__global__ void k_twiddle() {
    int j = blockIdx.x * blockDim.x + threadIdx.x;
    if (j < LL) {
        double a = -6.283185307179586476925286766559 * (double)j / (double)LL;
        g_tw[j] = make_float2((float)cos(a), (float)sin(a));
    }
}

// ---------------------------------------------------------------------------
// Mixed-radix Stockham FFT: five radix-4 stages (s = 4^j, shift/mask
// indexing, stage-invariant coalesced reads) then one twiddle-free radix-3
// stage (p = 0). Same verified DIF recurrence as before — read
// px[q+s(p+l*m)], write py[q+s(r*p+j)], twiddle g_tw[j*p*s] — only the radix
// schedule changed (3072 = 4^5 * 3).
// SGN=+1 forward, SGN=-1 inverse (unnormalized). Result ends in p0.
// ---------------------------------------------------------------------------
__device__ __forceinline__ float2 cmul(float2 a, float2 b) {
    return make_float2(a.x * b.x - a.y * b.y, a.x * b.y + a.y * b.x);
}

template <int SGN>
__device__ float2* block_fft(float2* p0, float2* p1, int tid, int nt)
{
    float2* px = p0;
    float2* py = p1;
#pragma unroll
    for (int j = 0; j < 5; j++) {
        const int s = 1 << (2 * j);
        for (int t = tid; t < 768; t += nt) {
            int q = t & (s - 1);
            int base = t - q;                 // p * s
            float2 a = px[t];
            float2 b = px[t + 768];
            float2 c = px[t + 1536];
            float2 d = px[t + 2304];
            float t0r = a.x + c.x, t0i = a.y + c.y;
            float t1r = a.x - c.x, t1i = a.y - c.y;
            float t2r = b.x + d.x, t2i = b.y + d.y;
            float t3r = b.x - d.x, t3i = b.y - d.y;
            float y1r, y1i, y3r, y3i;
            if (SGN > 0) { y1r = t1r + t3i; y1i = t1i - t3r;
                           y3r = t1r - t3i; y3i = t1i + t3r; }
            else         { y1r = t1r - t3i; y1i = t1i + t3r;
                           y3r = t1r + t3i; y3i = t1i - t3r; }
            float2 w1 = g_tw[base];        if (SGN < 0) w1.y = -w1.y;
            float2 w2 = g_tw[2 * base];    if (SGN < 0) w2.y = -w2.y;
            float2 w3 = g_tw[3 * base];    if (SGN < 0) w3.y = -w3.y;
            int o = 4 * base + q;
            py[o]         = make_float2(t0r + t2r, t0i + t2i);
            py[o + s]     = cmul(make_float2(y1r, y1i), w1);
            py[o + 2 * s] = cmul(make_float2(t0r - t2r, t0i - t2i), w2);
            py[o + 3 * s] = cmul(make_float2(y3r, y3i), w3);
        }
        __syncthreads();
        float2* tp = px; px = py; py = tp;
    }
    // final radix-3 stage: s=1024, m=1 -> p=0, twiddle-free
    {
        const float s0 = (SGN > 0) ? -0.86602540378443864676f
                                   :  0.86602540378443864676f;
        for (int q = tid; q < 1024; q += nt) {
            float2 a = px[q], b = px[q + 1024], c = px[q + 2048];
            float ur = b.x + c.x, ui = b.y + c.y;
            float dr = b.x - c.x, di = b.y - c.y;
            float vr = a.x - 0.5f * ur, vi = a.y - 0.5f * ui;
            float wr = -s0 * di, wi = s0 * dr;
            py[q]        = make_float2(a.x + ur, a.y + ui);
            py[q + 1024] = make_float2(vr + wr, vi + wi);
            py[q + 2048] = make_float2(vr - wr, vi - wi);
        }
        __syncthreads();
    }
    return py;   // 5 swaps: px==p1 after loop; radix-3 writes py==p0
}

// ---------------------------------------------------------------------------
// Forward FFT of q,k packed as z = q + i*k; write qhat * conj(khat)
// ---------------------------------------------------------------------------
__global__ __launch_bounds__(256) void k_fft()
{
    __shared__ __align__(16) float2 pool[2 * LL];
    float2* p0 = pool;
    float2* p1 = pool + LL;

    const int bc = blockIdx.x;
    const float* qr = g_Qt + (size_t)bc * LL;
    const float* kr = g_Kt + (size_t)bc * LL;
    const int tid = threadIdx.x;

    for (int i = tid; i < LL; i += 256) p0[i] = make_float2(qr[i], kr[i]);
    __syncthreads();

    float2* z = block_fft<1>(p0, p1, tid, 256);   // z == p0

    float2* P = g_P + (size_t)bc * NF;
    for (int f = tid; f < NF; f += 256) {
        float2 zf = z[f];
        int ridx = (f == 0) ? 0 : (LL - f);
        float2 zr = z[ridx];
        float qre = 0.5f * (zf.x + zr.x);
        float qim = 0.5f * (zf.y - zr.y);
        float dr = zf.x - zr.x;
        float di = zf.y + zr.y;
        float kre = 0.5f * di;
        float kim = -0.5f * dr;
        P[f] = make_float2(qre * kre + qim * kim, qim * kre - qre * kim);
    }
}

// ---------------------------------------------------------------------------
// Deterministic channel reduction: S[b,f] = sum_c P[b,c,f]
// ---------------------------------------------------------------------------
__global__ __launch_bounds__(256) void k_reduce()
{
    __shared__ float red[2][8][32];
    const int b    = blockIdx.y;
    const int lane = threadIdx.x & 31;
    const int cw   = threadIdx.x >> 5;
    const int f    = blockIdx.x * 32 + lane;

    float sr = 0.0f, si = 0.0f;
    if (f < NF) {
        for (int c = cw; c < DD; c += 8) {
            float2 v = g_P[((size_t)b * DD + c) * NF + f];
            sr += v.x; si += v.y;
        }
    }
    red[0][cw][lane] = sr;
    red[1][cw][lane] = si;
    __syncthreads();
    if (cw == 0 && f < NF) {
        float ar = 0.0f, ai = 0.0f;
#pragma unroll
        for (int w = 0; w < 8; w++) { ar += red[0][w][lane]; ai += red[1][w][lane]; }
        g_S[b * NF + f] = make_float2(ar, ai);
    }
}

// ---------------------------------------------------------------------------
// Per-batch inverse FFT -> mean_value, top-8 + softmax
// ---------------------------------------------------------------------------
__global__ __launch_bounds__(512) void k_ifft_topk()
{
    __shared__ __align__(16) float2 pool[2 * LL];
    float2* p0 = pool;
    float2* p1 = pool + LL;

    const int b = blockIdx.x;
    const int tid = threadIdx.x;
    const int nt = 512;

    for (int f = tid; f < LL; f += nt) {
        float2 v;
        if (f < NF) v = g_S[b * NF + f];
        else {
            float2 u = g_S[b * NF + (LL - f)];
            v = make_float2(u.x, -u.y);
        }
        p0[f] = v;
    }
    __syncthreads();

    float2* z = block_fft<-1>(p0, p1, tid, nt);   // z == p0

    // scratch lives in p1 (z occupies p0)
    float* meanArr = (float*)(pool + LL);
    float* redV    = meanArr + 3072;
    int*   redI    = (int*)(meanArr + 3584);

    const float scale = 1.0f / ((float)LL * (float)DD);
    for (int i = tid; i < LL; i += nt) meanArr[i] = z[i].x * scale;
    __syncthreads();

    float lw[TOPK];
    int   ld[TOPK];
    for (int k = 0; k < TOPK; k++) {
        float bv = -1e30f;
        int   bi = 0x7fffffff;
        for (int i = tid; i < LL; i += nt) {
            float v = meanArr[i];
            if (v > bv || (v == bv && i < bi)) { bv = v; bi = i; }
        }
        redV[tid] = bv; redI[tid] = bi;
        __syncthreads();
        for (int off = 256; off > 0; off >>= 1) {
            if (tid < off) {
                float v2 = redV[tid + off];
                int   i2 = redI[tid + off];
                if (v2 > redV[tid] || (v2 == redV[tid] && i2 < redI[tid])) {
                    redV[tid] = v2; redI[tid] = i2;
                }
            }
            __syncthreads();
        }
        if (tid == 0) {
            lw[k] = redV[0];
            ld[k] = redI[0];
            meanArr[redI[0]] = -1e30f;
        }
        __syncthreads();
    }

    if (tid == 0) {
        float mx = lw[0];
        for (int i = 1; i < TOPK; i++) mx = fmaxf(mx, lw[i]);
        float e[TOPK];
        float sum = 0.0f;
        for (int i = 0; i < TOPK; i++) { e[i] = expf(lw[i] - mx); sum += e[i]; }
        for (int i = 0; i < TOPK; i++) {
            g_w[b * TOPK + i] = e[i] / sum;
            g_d[b * TOPK + i] = ld[i];
        }
    }
}

// ---------------------------------------------------------------------------
// Time-delay aggregation over Y (Y already includes Wo and bo; sum w_i = 1):
//   Out[b][s][c] = sum_i w[b,i] * Y[b][(s+d_i)%L][c]
// grid (L, B), 256 threads; pure float4 gather, no requantization.
// ---------------------------------------------------------------------------
__global__ __launch_bounds__(256) void k_agg(float* __restrict__ Out)
{
    __shared__ float ws[TOPK];
    __shared__ int   ds[TOPK];
    const int s = blockIdx.x;
    const int b = blockIdx.y;
    const int tid = threadIdx.x;
    if (tid < TOPK) { ws[tid] = g_w[b * TOPK + tid]; ds[tid] = g_d[b * TOPK + tid]; }
    __syncthreads();

    const float* Yb = g_V + (size_t)b * LL * DD;
    const int c = tid * 4;
    float4 acc = make_float4(0.f, 0.f, 0.f, 0.f);
#pragma unroll
    for (int i = 0; i < TOPK; i++) {
        int j = s + ds[i];
        if (j >= LL) j -= LL;
        float4 v = *(const float4*)(Yb + (size_t)j * DD + c);
        float w = ws[i];
        acc.x += w * v.x; acc.y += w * v.y; acc.z += w * v.z; acc.w += w * v.w;
    }
    *(float4*)(Out + ((size_t)b * LL + s) * DD + c) = acc;
}

// ---------------------------------------------------------------------------
// kernel_launch
// ---------------------------------------------------------------------------
extern "C" void kernel_launch(void* const* d_in, const int* in_sizes, int n_in,
                              void* d_out, int out_size)
{
    const float* queries = (const float*)d_in[0];
    const float* keys    = (const float*)d_in[1];
    const float* values  = (const float*)d_in[2];
    const float* Wq = (const float*)d_in[3];
    const float* bq = (const float*)d_in[4];
    const float* Wk = (const float*)d_in[5];
    const float* bk = (const float*)d_in[6];
    const float* Wv = (const float*)d_in[7];
    const float* bv = (const float*)d_in[8];
    const float* Wo = (const float*)d_in[9];
    const float* bo = (const float*)d_in[10];
    float* Out = (float*)d_out;

    (void)in_sizes; (void)n_in; (void)out_size;

    const int dynC = NSTG * BUF_SZ;   // 98304 (>= epilogue's 128*132*4 = 67584)
    cudaFuncSetAttribute(k_gemm, cudaFuncAttributeMaxDynamicSharedMemorySize, dynC);

    k_twiddle<<<(LL + 255) / 256, 256>>>();
    k_wconv<<<dim3(32, 32, 4), dim3(32, 8)>>>(Wq, Wk, Wv, Wo);

    const int nsplit = (int)((size_t)MTOT * DD / 1024);   // 24576 blocks
    k_asplit3<<<dim3(nsplit, 3), 256>>>((const float4*)queries,
                                        (const float4*)keys,
                                        (const float4*)values);

    // fused Q/K/V projection GEMMs (z selects operand set + output mode;
    // Q/K single-limb A; V two-limb A, writes V's fp16 limbs into region 0)
    k_gemm<<<dim3(DD / 128, MTOT / 128, 3), 256, dynC>>>(
        0, 0, bq, bk, bv, Out, 0, 1, 2);

    // Y = V @ Wo + bo (two-limb A from region 0) -> g_V
    k_gemm<<<dim3(DD / 128, MTOT / 128, 1), 256, dynC>>>(
        0, 3, bo, bo, bo, Out, 3, 0, 2);

    k_fft<<<BB * DD, 256>>>();
    k_reduce<<<dim3((NF + 31) / 32, BB), 256>>>();
    k_ifft_topk<<<BB, 512>>>();
    k_agg<<<dim3(LL, BB), 256>>>(Out);
}

// round 14
// speedup vs baseline: 4.3993x; 1.2180x over previous
#include <cuda_runtime.h>
#include <cuda_fp16.h>
#include <math.h>
#include <stdint.h>

// Problem constants
#define BB   8
#define LL   3072
#define DD   1024
#define TOPK 8
#define NF   1537          // LL/2 + 1

#define MTOT (BB * LL)     // 24576

// ---------------------------------------------------------------------------
// Static device scratch
// ---------------------------------------------------------------------------
__device__ float  g_Qt[(size_t)BB * DD * LL];     // q projected, [B][D][L]
__device__ float  g_Kt[(size_t)BB * DD * LL];     // k projected, [B][D][L]
__device__ float  g_V [(size_t)BB * LL * DD];     // Y = V@Wo + bo, [B][L][D]
__device__ float2 g_P[(size_t)BB * DD * NF];
__device__ float2 g_S[BB * NF];
__device__ float2 g_tw[LL];
__device__ float  g_w[BB * TOPK];
__device__ int    g_d[BB * TOPK];
// fp16 A operands (single limb): regions 0..2. asplit writes Q->0, K->1,
// V->2. V-projection epilogue writes fp16(V) into region 0 for the Y-GEMM.
__device__ __align__(16) __half g_Ah[(size_t)3 * MTOT * DD];
__device__ __align__(16) __half g_Bh[(size_t)4 * DD * DD];   // Bh[n][k] = W[k][n]

// ---------------------------------------------------------------------------
// PTX helpers (all base-ISA; no 'a'-suffix features)
// ---------------------------------------------------------------------------
__device__ __forceinline__ uint32_t smem_u32(const void* p) {
    uint32_t a;
    asm("{ .reg .u64 t; cvta.to.shared.u64 t, %1; cvt.u32.u64 %0, t; }"
        : "=r"(a) : "l"(p));
    return a;
}
__device__ __forceinline__ void cp16(uint32_t s, const void* g) {
    asm volatile("cp.async.cg.shared.global [%0], [%1], 16;" :: "r"(s), "l"(g));
}
__device__ __forceinline__ void cp_commit() {
    asm volatile("cp.async.commit_group;");
}
// Not volatile — pure data ops; lets the scheduler hoist/interleave.
__device__ __forceinline__ void ldmx4(uint32_t* r, uint32_t a) {
    asm("ldmatrix.sync.aligned.m8n8.x4.shared.b16 {%0,%1,%2,%3}, [%4];"
        : "=r"(r[0]), "=r"(r[1]), "=r"(r[2]), "=r"(r[3]) : "r"(a));
}
__device__ __forceinline__ void mma16816(float* d, const uint32_t* a,
                                         uint32_t b0, uint32_t b1) {
    asm("mma.sync.aligned.m16n8k16.row.col.f32.f16.f16.f32 "
        "{%0,%1,%2,%3}, {%4,%5,%6,%7}, {%8,%9}, {%0,%1,%2,%3};"
        : "+f"(d[0]), "+f"(d[1]), "+f"(d[2]), "+f"(d[3])
        : "r"(a[0]), "r"(a[1]), "r"(a[2]), "r"(a[3]), "r"(b0), "r"(b1));
}
__device__ __forceinline__ uint32_t packh2(__half a, __half b) {
    __half2 t = __halves2half2(a, b);
    return *(uint32_t*)&t;
}

// ---------------------------------------------------------------------------
// Weight transpose + fp16 convert:  Bh[n][k] = fp16(W[k][n])
// grid (32, 32, 4), block (32, 8)
// ---------------------------------------------------------------------------
__global__ void k_wconv(const float* __restrict__ W0, const float* __restrict__ W1,
                        const float* __restrict__ W2, const float* __restrict__ W3)
{
    __shared__ float t[32][33];
    int z = blockIdx.z;
    const float* W = (z == 0) ? W0 : (z == 1) ? W1 : (z == 2) ? W2 : W3;
    __half* Bh = g_Bh + (size_t)z * DD * DD;
    int n0 = blockIdx.x * 32, k0 = blockIdx.y * 32;
    int tx = threadIdx.x, ty = threadIdx.y;
#pragma unroll
    for (int j = 0; j < 32; j += 8)
        t[ty + j][tx] = W[(size_t)(k0 + ty + j) * DD + n0 + tx];
    __syncthreads();
#pragma unroll
    for (int j = 0; j < 32; j += 8)
        Bh[(size_t)(n0 + ty + j) * DD + k0 + tx] = __float2half_rn(t[tx][ty + j]);
}

// ---------------------------------------------------------------------------
// A convert for Q,K,V in one launch: fp32 -> fp16 into region blockIdx.y.
// ---------------------------------------------------------------------------
__global__ __launch_bounds__(256) void k_asplit3(
    const float4* __restrict__ X0, const float4* __restrict__ X1,
    const float4* __restrict__ X2)
{
    const int reg = blockIdx.y;
    const float4* X = (reg == 0) ? X0 : (reg == 1) ? X1 : X2;
    size_t i = (size_t)blockIdx.x * 256 + threadIdx.x;
    float4 v = X[i];
    __half h0 = __float2half_rn(v.x), h1 = __float2half_rn(v.y);
    __half h2 = __float2half_rn(v.z), h3 = __float2half_rn(v.w);
    size_t o = (size_t)reg * (MTOT * DD / 4) + i;
    ((uint2*)g_Ah)[o] = make_uint2(packh2(h0, h1), packh2(h2, h3));
}

// ---------------------------------------------------------------------------
// Tensor-core GEMM (mma.sync fp16, single limb):
//   C[m][n] = sum_k Ah[m][k] * Bh[n][k]  + bias[n]
// CTA tile 128x128, KC=64 (4 k16 steps), double-buffered cp.async,
// 8 warps (4m x 2n), warp tile 32x64, 16 distinct accumulators/warp.
// SMEM/stage 32KB: A[16KB] B[16KB]; 128B rows, 16B-seg XOR swizzle.
// zsel: derive (areg,widx,mode) from blockIdx.z (fused Q/K/V launch).
// modes: 0/1 -> transposed g_Qt/g_Kt; 2 -> fp16 into region 0 (V-proj);
//        3 -> float natural into g_V (Y = V@Wo + bo).
// ---------------------------------------------------------------------------
#define KC 64
#define NCH (DD / KC)      // 16 chunks
#define OFF_B  16384
#define BUF_SZ 32768
#define NSTG 2

__global__ __launch_bounds__(256, 2)
void k_gemm(int areg, int widx, const float* __restrict__ bias0,
            const float* __restrict__ bias1, const float* __restrict__ bias2,
            int mode, int zsel)
{
    extern __shared__ __align__(16) char smem[];
    __shared__ float s_bias[128];

    if (zsel) { areg = blockIdx.z; widx = blockIdx.z; mode = blockIdx.z; }
    const float* bias = (widx == 1) ? bias1 : (widx == 2) ? bias2 : bias0;

    const int tid  = threadIdx.x;
    const int wid  = tid >> 5;
    const int lane = tid & 31;
    const int n0 = blockIdx.x * 128;
    const int m0 = blockIdx.y * 128;
    const int mw = wid >> 1;      // 0..3
    const int nw = wid & 1;       // 0..1

    const __half* Ah = g_Ah + (size_t)areg * MTOT * DD;
    const __half* Bh = g_Bh + (size_t)widx * DD * DD;

    if (tid < 128) s_bias[tid] = bias[n0 + tid];

    const uint32_t sbase = smem_u32(smem);

    float acc[2][8][4];
#pragma unroll
    for (int i = 0; i < 2; i++)
#pragma unroll
        for (int j = 0; j < 8; j++)
#pragma unroll
            for (int q = 0; q < 4; q++) acc[i][j][q] = 0.0f;

    // ---- async load of one KC=64 chunk into stage b ----
    auto load_chunk = [&](int c, int b) {
        uint32_t sb = sbase + b * BUF_SZ;
        const int k0 = c * KC;
#pragma unroll
        for (int u = 0; u < 4; u++) {
            int idx = tid * 4 + u;           // [0, 1024)
            int row = idx >> 3;
            int seg = idx & 7;
            uint32_t so = (uint32_t)(row * 128 + ((seg ^ (row & 7)) * 16));
            cp16(sb + so,         Ah + (size_t)(m0 + row) * DD + k0 + seg * 8);
            cp16(sb + OFF_B + so, Bh + (size_t)(n0 + row) * DD + k0 + seg * 8);
        }
        cp_commit();
    };

    load_chunk(0, 0);

    for (int c = 0; c < NCH; c++) {
        if (c + 1 < NCH) {
            load_chunk(c + 1, (c + 1) & 1);
            asm volatile("cp.async.wait_group 1;");
        } else {
            asm volatile("cp.async.wait_group 0;");
        }
        __syncthreads();

        const uint32_t bufu = sbase + (c & 1) * BUF_SZ;

#pragma unroll
        for (int ks = 0; ks < 4; ks++) {
            uint32_t a1f[2][4];
            const int arow0 = mw * 32 + (lane & 15);
            const int sega  = ks * 2 + (lane >> 4);
#pragma unroll
            for (int mi = 0; mi < 2; mi++) {
                int row = arow0 + mi * 16;
                ldmx4(a1f[mi], bufu + row * 128 + ((sega ^ (row & 7)) * 16));
            }
            const int nrow0 = nw * 64 + ((lane >> 4) & 1) * 8 + (lane & 7);
            const int segb  = ks * 2 + ((lane >> 3) & 1);
            uint32_t bf[4][4];
#pragma unroll
            for (int gi = 0; gi < 4; gi++) {
                int nrow = nrow0 + gi * 16;
                ldmx4(bf[gi], bufu + OFF_B + nrow * 128 + ((segb ^ (nrow & 7)) * 16));
            }
#pragma unroll
            for (int gi = 0; gi < 4; gi++)
#pragma unroll
                for (int half = 0; half < 2; half++)
#pragma unroll
                    for (int mi = 0; mi < 2; mi++)
                        mma16816(acc[mi][gi * 2 + half], a1f[mi],
                                 bf[gi][half * 2], bf[gi][half * 2 + 1]);
        }
        __syncthreads();
    }

    // ---- Epilogue: stage C tile (128 x 132 fp32) in smem, write coalesced ----
    float* smemC = (float*)smem;
#pragma unroll
    for (int mi = 0; mi < 2; mi++) {
        int r0 = mw * 32 + mi * 16 + (lane >> 2);
#pragma unroll
        for (int ni = 0; ni < 8; ni++) {
            int col = nw * 64 + ni * 8 + (lane & 3) * 2;
            smemC[r0 * 132 + col]           = acc[mi][ni][0];
            smemC[r0 * 132 + col + 1]       = acc[mi][ni][1];
            smemC[(r0 + 8) * 132 + col]     = acc[mi][ni][2];
            smemC[(r0 + 8) * 132 + col + 1] = acc[mi][ni][3];
        }
    }
    __syncthreads();

    if (mode <= 1) {
        float* dstT = (mode == 0) ? g_Qt : g_Kt;
        const int bB = m0 / LL;
        const int s0 = m0 - bB * LL;
#pragma unroll
        for (int i = 0; i < 16; i++) {
            int col = wid * 16 + i;
            float bi = s_bias[col];
            float4 o;
            o.x = smemC[(lane * 4 + 0) * 132 + col] + bi;
            o.y = smemC[(lane * 4 + 1) * 132 + col] + bi;
            o.z = smemC[(lane * 4 + 2) * 132 + col] + bi;
            o.w = smemC[(lane * 4 + 3) * 132 + col] + bi;
            *(float4*)&dstT[((size_t)bB * DD + n0 + col) * LL + s0 + lane * 4] = o;
        }
    } else if (mode == 2) {
        // V projection: write fp16(C + bias) into region 0 for the Y-GEMM
        const int row = tid >> 1;
        const int cb  = (tid & 1) * 64;
        const size_t rb = (size_t)(m0 + row) * DD + n0 + cb;
#pragma unroll
        for (int i = 0; i < 16; i++) {
            float4 v = *(float4*)&smemC[row * 132 + cb + i * 4];
            v.x += s_bias[cb + i * 4 + 0];
            v.y += s_bias[cb + i * 4 + 1];
            v.z += s_bias[cb + i * 4 + 2];
            v.w += s_bias[cb + i * 4 + 3];
            __half h0 = __float2half_rn(v.x), h1 = __float2half_rn(v.y);
            __half h2 = __float2half_rn(v.z), h3 = __float2half_rn(v.w);
            *(uint2*)(g_Ah + rb + i * 4) = make_uint2(packh2(h0, h1), packh2(h2, h3));
        }
    } else {
        // Y = V @ Wo + bo, float natural layout into g_V
        const int row = tid >> 1;
        const int cb  = (tid & 1) * 64;
        const size_t rb = (size_t)(m0 + row) * DD + n0 + cb;
#pragma unroll
        for (int i = 0; i < 16; i++) {
            float4 v = *(float4*)&smemC[row * 132 + cb + i * 4];
            v.x += s_bias[cb + i * 4 + 0];
            v.y += s_bias[cb + i * 4 + 1];
            v.z += s_bias[cb + i * 4 + 2];
            v.w += s_bias[cb + i * 4 + 3];
            *(float4*)&g_V[rb + i * 4] = v;
        }
    }
}

// ---------------------------------------------------------------------------
// Twiddle init
// ---------------------------------------------------------------------------
__global__ void k_twiddle() {
    int j = blockIdx.x * blockDim.x + threadIdx.x;
    if (j < LL) {
        double a = -6.283185307179586476925286766559 * (double)j / (double)LL;
        g_tw[j] = make_float2((float)cos(a), (float)sin(a));
    }
}

// ---------------------------------------------------------------------------
// Mixed-radix Stockham FFT: five radix-4 stages (s = 4^j, shift/mask
// indexing, stage-invariant coalesced reads) then one twiddle-free radix-3
// stage (p = 0). SGN=+1 forward, SGN=-1 inverse (unnormalized). Ends in p0.
// ---------------------------------------------------------------------------
__device__ __forceinline__ float2 cmul(float2 a, float2 b) {
    return make_float2(a.x * b.x - a.y * b.y, a.x * b.y + a.y * b.x);
}

template <int SGN>
__device__ float2* block_fft(float2* p0, float2* p1, int tid, int nt)
{
    float2* px = p0;
    float2* py = p1;
#pragma unroll
    for (int j = 0; j < 5; j++) {
        const int s = 1 << (2 * j);
        for (int t = tid; t < 768; t += nt) {
            int q = t & (s - 1);
            int base = t - q;                 // p * s
            float2 a = px[t];
            float2 b = px[t + 768];
            float2 c = px[t + 1536];
            float2 d = px[t + 2304];
            float t0r = a.x + c.x, t0i = a.y + c.y;
            float t1r = a.x - c.x, t1i = a.y - c.y;
            float t2r = b.x + d.x, t2i = b.y + d.y;
            float t3r = b.x - d.x, t3i = b.y - d.y;
            float y1r, y1i, y3r, y3i;
            if (SGN > 0) { y1r = t1r + t3i; y1i = t1i - t3r;
                           y3r = t1r - t3i; y3i = t1i + t3r; }
            else         { y1r = t1r - t3i; y1i = t1i + t3r;
                           y3r = t1r + t3i; y3i = t1i - t3r; }
            float2 w1 = g_tw[base];        if (SGN < 0) w1.y = -w1.y;
            float2 w2 = g_tw[2 * base];    if (SGN < 0) w2.y = -w2.y;
            float2 w3 = g_tw[3 * base];    if (SGN < 0) w3.y = -w3.y;
            int o = 4 * base + q;
            py[o]         = make_float2(t0r + t2r, t0i + t2i);
            py[o + s]     = cmul(make_float2(y1r, y1i), w1);
            py[o + 2 * s] = cmul(make_float2(t0r - t2r, t0i - t2i), w2);
            py[o + 3 * s] = cmul(make_float2(y3r, y3i), w3);
        }
        __syncthreads();
        float2* tp = px; px = py; py = tp;
    }
    // final radix-3 stage: s=1024, m=1 -> p=0, twiddle-free
    {
        const float s0 = (SGN > 0) ? -0.86602540378443864676f
                                   :  0.86602540378443864676f;
        for (int q = tid; q < 1024; q += nt) {
            float2 a = px[q], b = px[q + 1024], c = px[q + 2048];
            float ur = b.x + c.x, ui = b.y + c.y;
            float dr = b.x - c.x, di = b.y - c.y;
            float vr = a.x - 0.5f * ur, vi = a.y - 0.5f * ui;
            float wr = -s0 * di, wi = s0 * dr;
            py[q]        = make_float2(a.x + ur, a.y + ui);
            py[q + 1024] = make_float2(vr + wr, vi + wi);
            py[q + 2048] = make_float2(vr - wr, vi - wi);
        }
        __syncthreads();
    }
    return py;   // 5 swaps: px==p1 after loop; radix-3 writes py==p0
}

// ---------------------------------------------------------------------------
// Forward FFT of q,k packed as z = q + i*k; write qhat * conj(khat)
// ---------------------------------------------------------------------------
__global__ __launch_bounds__(256) void k_fft()
{
    __shared__ __align__(16) float2 pool[2 * LL];
    float2* p0 = pool;
    float2* p1 = pool + LL;

    const int bc = blockIdx.x;
    const float* qr = g_Qt + (size_t)bc * LL;
    const float* kr = g_Kt + (size_t)bc * LL;
    const int tid = threadIdx.x;

    for (int i = tid; i < LL; i += 256) p0[i] = make_float2(qr[i], kr[i]);
    __syncthreads();

    float2* z = block_fft<1>(p0, p1, tid, 256);   // z == p0

    float2* P = g_P + (size_t)bc * NF;
    for (int f = tid; f < NF; f += 256) {
        float2 zf = z[f];
        int ridx = (f == 0) ? 0 : (LL - f);
        float2 zr = z[ridx];
        float qre = 0.5f * (zf.x + zr.x);
        float qim = 0.5f * (zf.y - zr.y);
        float dr = zf.x - zr.x;
        float di = zf.y + zr.y;
        float kre = 0.5f * di;
        float kim = -0.5f * dr;
        P[f] = make_float2(qre * kre + qim * kim, qim * kre - qre * kim);
    }
}

// ---------------------------------------------------------------------------
// Deterministic channel reduction: S[b,f] = sum_c P[b,c,f]
// ---------------------------------------------------------------------------
__global__ __launch_bounds__(256) void k_reduce()
{
    __shared__ float red[2][8][32];
    const int b    = blockIdx.y;
    const int lane = threadIdx.x & 31;
    const int cw   = threadIdx.x >> 5;
    const int f    = blockIdx.x * 32 + lane;

    float sr = 0.0f, si = 0.0f;
    if (f < NF) {
        for (int c = cw; c < DD; c += 8) {
            float2 v = g_P[((size_t)b * DD + c) * NF + f];
            sr += v.x; si += v.y;
        }
    }
    red[0][cw][lane] = sr;
    red[1][cw][lane] = si;
    __syncthreads();
    if (cw == 0 && f < NF) {
        float ar = 0.0f, ai = 0.0f;
#pragma unroll
        for (int w = 0; w < 8; w++) { ar += red[0][w][lane]; ai += red[1][w][lane]; }
        g_S[b * NF + f] = make_float2(ar, ai);
    }
}

// ---------------------------------------------------------------------------
// Per-batch inverse FFT -> mean_value, top-8 + softmax
// ---------------------------------------------------------------------------
__global__ __launch_bounds__(512) void k_ifft_topk()
{
    __shared__ __align__(16) float2 pool[2 * LL];
    float2* p0 = pool;
    float2* p1 = pool + LL;

    const int b = blockIdx.x;
    const int tid = threadIdx.x;
    const int nt = 512;

    for (int f = tid; f < LL; f += nt) {
        float2 v;
        if (f < NF) v = g_S[b * NF + f];
        else {
            float2 u = g_S[b * NF + (LL - f)];
            v = make_float2(u.x, -u.y);
        }
        p0[f] = v;
    }
    __syncthreads();

    float2* z = block_fft<-1>(p0, p1, tid, nt);   // z == p0

    // scratch lives in p1 (z occupies p0)
    float* meanArr = (float*)(pool + LL);
    float* redV    = meanArr + 3072;
    int*   redI    = (int*)(meanArr + 3584);

    const float scale = 1.0f / ((float)LL * (float)DD);
    for (int i = tid; i < LL; i += nt) meanArr[i] = z[i].x * scale;
    __syncthreads();

    float lw[TOPK];
    int   ld[TOPK];
    for (int k = 0; k < TOPK; k++) {
        float bv = -1e30f;
        int   bi = 0x7fffffff;
        for (int i = tid; i < LL; i += nt) {
            float v = meanArr[i];
            if (v > bv || (v == bv && i < bi)) { bv = v; bi = i; }
        }
        redV[tid] = bv; redI[tid] = bi;
        __syncthreads();
        for (int off = 256; off > 0; off >>= 1) {
            if (tid < off) {
                float v2 = redV[tid + off];
                int   i2 = redI[tid + off];
                if (v2 > redV[tid] || (v2 == redV[tid] && i2 < redI[tid])) {
                    redV[tid] = v2; redI[tid] = i2;
                }
            }
            __syncthreads();
        }
        if (tid == 0) {
            lw[k] = redV[0];
            ld[k] = redI[0];
            meanArr[redI[0]] = -1e30f;
        }
        __syncthreads();
    }

    if (tid == 0) {
        float mx = lw[0];
        for (int i = 1; i < TOPK; i++) mx = fmaxf(mx, lw[i]);
        float e[TOPK];
        float sum = 0.0f;
        for (int i = 0; i < TOPK; i++) { e[i] = expf(lw[i] - mx); sum += e[i]; }
        for (int i = 0; i < TOPK; i++) {
            g_w[b * TOPK + i] = e[i] / sum;
            g_d[b * TOPK + i] = ld[i];
        }
    }
}

// ---------------------------------------------------------------------------
// Time-delay aggregation over Y (Y already includes Wo and bo; sum w_i = 1):
//   Out[b][s][c] = sum_i w[b,i] * Y[b][(s+d_i)%L][c]
// grid (L, B), 256 threads; pure float4 gather.
// ---------------------------------------------------------------------------
__global__ __launch_bounds__(256) void k_agg(float* __restrict__ Out)
{
    __shared__ float ws[TOPK];
    __shared__ int   ds[TOPK];
    const int s = blockIdx.x;
    const int b = blockIdx.y;
    const int tid = threadIdx.x;
    if (tid < TOPK) { ws[tid] = g_w[b * TOPK + tid]; ds[tid] = g_d[b * TOPK + tid]; }
    __syncthreads();

    const float* Yb = g_V + (size_t)b * LL * DD;
    const int c = tid * 4;
    float4 acc = make_float4(0.f, 0.f, 0.f, 0.f);
#pragma unroll
    for (int i = 0; i < TOPK; i++) {
        int j = s + ds[i];
        if (j >= LL) j -= LL;
        float4 v = *(const float4*)(Yb + (size_t)j * DD + c);
        float w = ws[i];
        acc.x += w * v.x; acc.y += w * v.y; acc.z += w * v.z; acc.w += w * v.w;
    }
    *(float4*)(Out + ((size_t)b * LL + s) * DD + c) = acc;
}

// ---------------------------------------------------------------------------
// kernel_launch
// ---------------------------------------------------------------------------
extern "C" void kernel_launch(void* const* d_in, const int* in_sizes, int n_in,
                              void* d_out, int out_size)
{
    const float* queries = (const float*)d_in[0];
    const float* keys    = (const float*)d_in[1];
    const float* values  = (const float*)d_in[2];
    const float* Wq = (const float*)d_in[3];
    const float* bq = (const float*)d_in[4];
    const float* Wk = (const float*)d_in[5];
    const float* bk = (const float*)d_in[6];
    const float* Wv = (const float*)d_in[7];
    const float* bv = (const float*)d_in[8];
    const float* Wo = (const float*)d_in[9];
    const float* bo = (const float*)d_in[10];
    float* Out = (float*)d_out;

    (void)in_sizes; (void)n_in; (void)out_size;

    // epilogue smem (128*132*4 = 67584) > 2 stages (65536)
    const int dynC = 128 * 132 * 4;
    cudaFuncSetAttribute(k_gemm, cudaFuncAttributeMaxDynamicSharedMemorySize, dynC);

    k_twiddle<<<(LL + 255) / 256, 256>>>();
    k_wconv<<<dim3(32, 32, 4), dim3(32, 8)>>>(Wq, Wk, Wv, Wo);

    const int nsplit = (int)((size_t)MTOT * DD / 1024);   // 24576 blocks
    k_asplit3<<<dim3(nsplit, 3), 256>>>((const float4*)queries,
                                        (const float4*)keys,
                                        (const float4*)values);

    // fused Q/K/V projection GEMMs (z selects operand set + output mode;
    // V-proj writes fp16(V) into region 0)
    k_gemm<<<dim3(DD / 128, MTOT / 128, 3), 256, dynC>>>(
        0, 0, bq, bk, bv, 0, 1);

    // Y = V @ Wo + bo (region 0) -> g_V
    k_gemm<<<dim3(DD / 128, MTOT / 128, 1), 256, dynC>>>(
        0, 3, bo, bo, bo, 3, 0);

    k_fft<<<BB * DD, 256>>>();
    k_reduce<<<dim3((NF + 31) / 32, BB), 256>>>();
    k_ifft_topk<<<BB, 512>>>();
    k_agg<<<dim3(LL, BB), 256>>>(Out);
}

// round 15
// speedup vs baseline: 5.3824x; 1.2234x over previous
#include <cuda_runtime.h>
#include <cuda_fp16.h>
#include <math.h>
#include <stdint.h>

// Problem constants
#define BB   8
#define LL   3072
#define DD   1024
#define TOPK 8
#define NF   1537          // LL/2 + 1
#define CHB  8             // channels per FFT block

#define MTOT (BB * LL)     // 24576

// ---------------------------------------------------------------------------
// Static device scratch
// ---------------------------------------------------------------------------
__device__ float  g_Qt[(size_t)BB * DD * LL];     // q projected, [B][D][L]
__device__ float  g_Kt[(size_t)BB * DD * LL];     // k projected, [B][D][L]
__device__ float  g_V [(size_t)BB * LL * DD];     // Y = V@Wo + bo, [B][L][D]
__device__ float2 g_P[(size_t)BB * (DD / CHB) * NF];  // partial spectra
__device__ float2 g_S[BB * NF];
__device__ float2 g_tw[LL];
__device__ float  g_w[BB * TOPK];
__device__ int    g_d[BB * TOPK];
// fp16 A operands (single limb): regions 0..2. asplit writes Q->0, K->1,
// V->2. V-projection epilogue writes fp16(V) into region 0 for the Y-GEMM.
__device__ __align__(16) __half g_Ah[(size_t)3 * MTOT * DD];
__device__ __align__(16) __half g_Bh[(size_t)4 * DD * DD];   // Bh[n][k] = W[k][n]

// ---------------------------------------------------------------------------
// PTX helpers (all base-ISA; no 'a'-suffix features)
// ---------------------------------------------------------------------------
__device__ __forceinline__ uint32_t smem_u32(const void* p) {
    uint32_t a;
    asm("{ .reg .u64 t; cvta.to.shared.u64 t, %1; cvt.u32.u64 %0, t; }"
        : "=r"(a) : "l"(p));
    return a;
}
__device__ __forceinline__ void cp16(uint32_t s, const void* g) {
    asm volatile("cp.async.cg.shared.global [%0], [%1], 16;" :: "r"(s), "l"(g));
}
__device__ __forceinline__ void cp_commit() {
    asm volatile("cp.async.commit_group;");
}
// Not volatile — pure data ops; lets the scheduler hoist/interleave.
__device__ __forceinline__ void ldmx4(uint32_t* r, uint32_t a) {
    asm("ldmatrix.sync.aligned.m8n8.x4.shared.b16 {%0,%1,%2,%3}, [%4];"
        : "=r"(r[0]), "=r"(r[1]), "=r"(r[2]), "=r"(r[3]) : "r"(a));
}
__device__ __forceinline__ void mma16816(float* d, const uint32_t* a,
                                         uint32_t b0, uint32_t b1) {
    asm("mma.sync.aligned.m16n8k16.row.col.f32.f16.f16.f32 "
        "{%0,%1,%2,%3}, {%4,%5,%6,%7}, {%8,%9}, {%0,%1,%2,%3};"
        : "+f"(d[0]), "+f"(d[1]), "+f"(d[2]), "+f"(d[3])
        : "r"(a[0]), "r"(a[1]), "r"(a[2]), "r"(a[3]), "r"(b0), "r"(b1));
}
__device__ __forceinline__ uint32_t packh2(__half a, __half b) {
    __half2 t = __halves2half2(a, b);
    return *(uint32_t*)&t;
}

// ---------------------------------------------------------------------------
// Weight transpose + fp16 convert:  Bh[n][k] = fp16(W[k][n])
// ---------------------------------------------------------------------------
__global__ void k_wconv(const float* __restrict__ W0, const float* __restrict__ W1,
                        const float* __restrict__ W2, const float* __restrict__ W3)
{
    __shared__ float t[32][33];
    int z = blockIdx.z;
    const float* W = (z == 0) ? W0 : (z == 1) ? W1 : (z == 2) ? W2 : W3;
    __half* Bh = g_Bh + (size_t)z * DD * DD;
    int n0 = blockIdx.x * 32, k0 = blockIdx.y * 32;
    int tx = threadIdx.x, ty = threadIdx.y;
#pragma unroll
    for (int j = 0; j < 32; j += 8)
        t[ty + j][tx] = W[(size_t)(k0 + ty + j) * DD + n0 + tx];
    __syncthreads();
#pragma unroll
    for (int j = 0; j < 32; j += 8)
        Bh[(size_t)(n0 + ty + j) * DD + k0 + tx] = __float2half_rn(t[tx][ty + j]);
}

// ---------------------------------------------------------------------------
// A convert for Q,K,V in one launch: fp32 -> fp16 into region blockIdx.y.
// ---------------------------------------------------------------------------
__global__ __launch_bounds__(256) void k_asplit3(
    const float4* __restrict__ X0, const float4* __restrict__ X1,
    const float4* __restrict__ X2)
{
    const int reg = blockIdx.y;
    const float4* X = (reg == 0) ? X0 : (reg == 1) ? X1 : X2;
    size_t i = (size_t)blockIdx.x * 256 + threadIdx.x;
    float4 v = X[i];
    __half h0 = __float2half_rn(v.x), h1 = __float2half_rn(v.y);
    __half h2 = __float2half_rn(v.z), h3 = __float2half_rn(v.w);
    size_t o = (size_t)reg * (MTOT * DD / 4) + i;
    ((uint2*)g_Ah)[o] = make_uint2(packh2(h0, h1), packh2(h2, h3));
}

// ---------------------------------------------------------------------------
// Tensor-core GEMM (mma.sync fp16, single limb):
//   C[m][n] = sum_k Ah[m][k] * Bh[n][k]  + bias[n]
// CTA tile 128x128, KC=64 (4 k16 steps), 3-stage cp.async pipeline with
// loads for chunk c+2 SPREAD across the 4 ks-steps of chunk c's compute
// (smooths LSU bursts; full-chunk latency cover).
// 8 warps (4m x 2n), warp tile 32x64, 16 distinct accumulators/warp.
// SMEM/stage 32KB: A[16KB] B[16KB]; 128B rows, 16B-seg XOR swizzle.
// zsel: derive (areg,widx,mode) from blockIdx.z (fused Q/K/V launch).
// modes: 0/1 -> transposed g_Qt/g_Kt; 2 -> fp16 into region 0 (V-proj);
//        3 -> float natural into g_V (Y = V@Wo + bo).
// ---------------------------------------------------------------------------
#define KC 64
#define NCH (DD / KC)      // 16 chunks
#define OFF_B  16384
#define BUF_SZ 32768
#define NSTG 3

__global__ __launch_bounds__(256, 2)
void k_gemm(int areg, int widx, const float* __restrict__ bias0,
            const float* __restrict__ bias1, const float* __restrict__ bias2,
            int mode, int zsel)
{
    extern __shared__ __align__(16) char smem[];
    __shared__ float s_bias[128];

    if (zsel) { areg = blockIdx.z; widx = blockIdx.z; mode = blockIdx.z; }
    const float* bias = (widx == 1) ? bias1 : (widx == 2) ? bias2 : bias0;

    const int tid  = threadIdx.x;
    const int wid  = tid >> 5;
    const int lane = tid & 31;
    const int n0 = blockIdx.x * 128;
    const int m0 = blockIdx.y * 128;
    const int mw = wid >> 1;      // 0..3
    const int nw = wid & 1;       // 0..1

    const __half* Ah = g_Ah + (size_t)areg * MTOT * DD;
    const __half* Bh = g_Bh + (size_t)widx * DD * DD;

    if (tid < 128) s_bias[tid] = bias[n0 + tid];

    const uint32_t sbase = smem_u32(smem);

    float acc[2][8][4];
#pragma unroll
    for (int i = 0; i < 2; i++)
#pragma unroll
        for (int j = 0; j < 8; j++)
#pragma unroll
            for (int q = 0; q < 4; q++) acc[i][j][q] = 0.0f;

    // one quarter (256 of 1024 16B-lines per array) of chunk loads
    auto load_quarter = [&](int k0n, uint32_t sbn, int ks) {
        int idx = ks * 256 + tid;        // [0, 1024)
        int row = idx >> 3;
        int seg = idx & 7;
        uint32_t so = (uint32_t)(row * 128 + ((seg ^ (row & 7)) * 16));
        cp16(sbn + so,         Ah + (size_t)(m0 + row) * DD + k0n + seg * 8);
        cp16(sbn + OFF_B + so, Bh + (size_t)(n0 + row) * DD + k0n + seg * 8);
    };
    auto load_chunk = [&](int c, int b) {
        uint32_t sb = sbase + b * BUF_SZ;
#pragma unroll
        for (int ks = 0; ks < 4; ks++) load_quarter(c * KC, sb, ks);
        cp_commit();
    };

    load_chunk(0, 0);
    load_chunk(1, 1);

    int bufc = 0;   // c % 3
    for (int c = 0; c < NCH; c++) {
        if (c + 1 < NCH) {
            asm volatile("cp.async.wait_group 1;");
        } else {
            asm volatile("cp.async.wait_group 0;");
        }
        __syncthreads();

        const uint32_t bufu = sbase + bufc * BUF_SZ;
        const int cn = c + 2;                      // chunk being prefetched
        int bn = bufc + 2; if (bn >= NSTG) bn -= NSTG;
        const uint32_t sbn = sbase + bn * BUF_SZ;
        const bool pf = (cn < NCH);

#pragma unroll
        for (int ks = 0; ks < 4; ks++) {
            uint32_t a1f[2][4];
            const int arow0 = mw * 32 + (lane & 15);
            const int sega  = ks * 2 + (lane >> 4);
#pragma unroll
            for (int mi = 0; mi < 2; mi++) {
                int row = arow0 + mi * 16;
                ldmx4(a1f[mi], bufu + row * 128 + ((sega ^ (row & 7)) * 16));
            }
            const int nrow0 = nw * 64 + ((lane >> 4) & 1) * 8 + (lane & 7);
            const int segb  = ks * 2 + ((lane >> 3) & 1);
            uint32_t bf[4][4];
#pragma unroll
            for (int gi = 0; gi < 4; gi++) {
                int nrow = nrow0 + gi * 16;
                ldmx4(bf[gi], bufu + OFF_B + nrow * 128 + ((segb ^ (nrow & 7)) * 16));
            }
            // interleave one quarter of the c+2 prefetch with this ks's MMAs
            if (pf) load_quarter(cn * KC, sbn, ks);
#pragma unroll
            for (int gi = 0; gi < 4; gi++)
#pragma unroll
                for (int half = 0; half < 2; half++)
#pragma unroll
                    for (int mi = 0; mi < 2; mi++)
                        mma16816(acc[mi][gi * 2 + half], a1f[mi],
                                 bf[gi][half * 2], bf[gi][half * 2 + 1]);
        }
        if (pf) cp_commit();
        bufc = (bufc + 1 == NSTG) ? 0 : bufc + 1;
    }
    __syncthreads();

    // ---- Epilogue: stage C tile (128 x 132 fp32) in smem, write coalesced ----
    float* smemC = (float*)smem;
#pragma unroll
    for (int mi = 0; mi < 2; mi++) {
        int r0 = mw * 32 + mi * 16 + (lane >> 2);
#pragma unroll
        for (int ni = 0; ni < 8; ni++) {
            int col = nw * 64 + ni * 8 + (lane & 3) * 2;
            smemC[r0 * 132 + col]           = acc[mi][ni][0];
            smemC[r0 * 132 + col + 1]       = acc[mi][ni][1];
            smemC[(r0 + 8) * 132 + col]     = acc[mi][ni][2];
            smemC[(r0 + 8) * 132 + col + 1] = acc[mi][ni][3];
        }
    }
    __syncthreads();

    if (mode <= 1) {
        float* dstT = (mode == 0) ? g_Qt : g_Kt;
        const int bB = m0 / LL;
        const int s0 = m0 - bB * LL;
#pragma unroll
        for (int i = 0; i < 16; i++) {
            int col = wid * 16 + i;
            float bi = s_bias[col];
            float4 o;
            o.x = smemC[(lane * 4 + 0) * 132 + col] + bi;
            o.y = smemC[(lane * 4 + 1) * 132 + col] + bi;
            o.z = smemC[(lane * 4 + 2) * 132 + col] + bi;
            o.w = smemC[(lane * 4 + 3) * 132 + col] + bi;
            *(float4*)&dstT[((size_t)bB * DD + n0 + col) * LL + s0 + lane * 4] = o;
        }
    } else if (mode == 2) {
        // V projection: write fp16(C + bias) into region 0 for the Y-GEMM
        const int row = tid >> 1;
        const int cb  = (tid & 1) * 64;
        const size_t rb = (size_t)(m0 + row) * DD + n0 + cb;
#pragma unroll
        for (int i = 0; i < 16; i++) {
            float4 v = *(float4*)&smemC[row * 132 + cb + i * 4];
            v.x += s_bias[cb + i * 4 + 0];
            v.y += s_bias[cb + i * 4 + 1];
            v.z += s_bias[cb + i * 4 + 2];
            v.w += s_bias[cb + i * 4 + 3];
            __half h0 = __float2half_rn(v.x), h1 = __float2half_rn(v.y);
            __half h2 = __float2half_rn(v.z), h3 = __float2half_rn(v.w);
            *(uint2*)(g_Ah + rb + i * 4) = make_uint2(packh2(h0, h1), packh2(h2, h3));
        }
    } else {
        // Y = V @ Wo + bo, float natural layout into g_V
        const int row = tid >> 1;
        const int cb  = (tid & 1) * 64;
        const size_t rb = (size_t)(m0 + row) * DD + n0 + cb;
#pragma unroll
        for (int i = 0; i < 16; i++) {
            float4 v = *(float4*)&smemC[row * 132 + cb + i * 4];
            v.x += s_bias[cb + i * 4 + 0];
            v.y += s_bias[cb + i * 4 + 1];
            v.z += s_bias[cb + i * 4 + 2];
            v.w += s_bias[cb + i * 4 + 3];
            *(float4*)&g_V[rb + i * 4] = v;
        }
    }
}

// ---------------------------------------------------------------------------
// Twiddle init
// ---------------------------------------------------------------------------
__global__ void k_twiddle() {
    int j = blockIdx.x * blockDim.x + threadIdx.x;
    if (j < LL) {
        double a = -6.283185307179586476925286766559 * (double)j / (double)LL;
        g_tw[j] = make_float2((float)cos(a), (float)sin(a));
    }
}

// ---------------------------------------------------------------------------
// Mixed-radix Stockham FFT: five radix-4 stages (s = 4^j, shift/mask
// indexing, stage-invariant coalesced reads) then one twiddle-free radix-3
// stage (p = 0). SGN=+1 forward, SGN=-1 inverse (unnormalized). Ends in p0.
// ---------------------------------------------------------------------------
__device__ __forceinline__ float2 cmul(float2 a, float2 b) {
    return make_float2(a.x * b.x - a.y * b.y, a.x * b.y + a.y * b.x);
}

template <int SGN>
__device__ float2* block_fft(float2* p0, float2* p1, int tid, int nt)
{
    float2* px = p0;
    float2* py = p1;
#pragma unroll
    for (int j = 0; j < 5; j++) {
        const int s = 1 << (2 * j);
        for (int t = tid; t < 768; t += nt) {
            int q = t & (s - 1);
            int base = t - q;                 // p * s
            float2 a = px[t];
            float2 b = px[t + 768];
            float2 c = px[t + 1536];
            float2 d = px[t + 2304];
            float t0r = a.x + c.x, t0i = a.y + c.y;
            float t1r = a.x - c.x, t1i = a.y - c.y;
            float t2r = b.x + d.x, t2i = b.y + d.y;
            float t3r = b.x - d.x, t3i = b.y - d.y;
            float y1r, y1i, y3r, y3i;
            if (SGN > 0) { y1r = t1r + t3i; y1i = t1i - t3r;
                           y3r = t1r - t3i; y3i = t1i + t3r; }
            else         { y1r = t1r - t3i; y1i = t1i + t3r;
                           y3r = t1r + t3i; y3i = t1i - t3r; }
            float2 w1 = g_tw[base];        if (SGN < 0) w1.y = -w1.y;
            float2 w2 = g_tw[2 * base];    if (SGN < 0) w2.y = -w2.y;
            float2 w3 = g_tw[3 * base];    if (SGN < 0) w3.y = -w3.y;
            int o = 4 * base + q;
            py[o]         = make_float2(t0r + t2r, t0i + t2i);
            py[o + s]     = cmul(make_float2(y1r, y1i), w1);
            py[o + 2 * s] = cmul(make_float2(t0r - t2r, t0i - t2i), w2);
            py[o + 3 * s] = cmul(make_float2(y3r, y3i), w3);
        }
        __syncthreads();
        float2* tp = px; px = py; py = tp;
    }
    // final radix-3 stage: s=1024, m=1 -> p=0, twiddle-free
    {
        const float s0 = (SGN > 0) ? -0.86602540378443864676f
                                   :  0.86602540378443864676f;
        for (int q = tid; q < 1024; q += nt) {
            float2 a = px[q], b = px[q + 1024], c = px[q + 2048];
            float ur = b.x + c.x, ui = b.y + c.y;
            float dr = b.x - c.x, di = b.y - c.y;
            float vr = a.x - 0.5f * ur, vi = a.y - 0.5f * ui;
            float wr = -s0 * di, wi = s0 * dr;
            py[q]        = make_float2(a.x + ur, a.y + ui);
            py[q + 1024] = make_float2(vr + wr, vi + wi);
            py[q + 2048] = make_float2(vr - wr, vi - wi);
        }
        __syncthreads();
    }
    return py;   // 5 swaps: px==p1 after loop; radix-3 writes py==p0
}

// ---------------------------------------------------------------------------
// Forward FFT of q,k packed as z = q + i*k for CHB=8 channels per block,
// with the channel reduction fused: accumulate qhat*conj(khat) in smem and
// write ONE partial spectrum per block (g_P traffic drops 8x).
// grid = BB*DD/CHB = 1024, 256 threads, 61.5KB dynamic smem.
// ---------------------------------------------------------------------------
__global__ __launch_bounds__(256) void k_fft()
{
    extern __shared__ __align__(16) float2 fsm[];
    float2* p0   = fsm;            // [0, LL)
    float2* p1   = fsm + LL;       // [LL, 2LL)
    float2* accS = fsm + 2 * LL;   // [2LL, 2LL+NF)

    const int blk = blockIdx.x;            // 0..1023
    const int tid = threadIdx.x;

    for (int f = tid; f < NF; f += 256) accS[f] = make_float2(0.f, 0.f);

    for (int ch = 0; ch < CHB; ch++) {
        size_t bc = (size_t)blk * CHB + ch;
        const float* qr = g_Qt + bc * LL;
        const float* kr = g_Kt + bc * LL;
        __syncthreads();   // previous iteration's accS readers done with p0
        for (int i = tid; i < LL; i += 256) p0[i] = make_float2(qr[i], kr[i]);
        __syncthreads();

        float2* z = block_fft<1>(p0, p1, tid, 256);   // z == p0

        for (int f = tid; f < NF; f += 256) {
            float2 zf = z[f];
            int ridx = (f == 0) ? 0 : (LL - f);
            float2 zr = z[ridx];
            float qre = 0.5f * (zf.x + zr.x);
            float qim = 0.5f * (zf.y - zr.y);
            float dr = zf.x - zr.x;
            float di = zf.y + zr.y;
            float kre = 0.5f * di;
            float kim = -0.5f * dr;
            float2 a = accS[f];
            a.x += qre * kre + qim * kim;
            a.y += qim * kre - qre * kim;
            accS[f] = a;
        }
    }
    __syncthreads();
    float2* P = g_P + (size_t)blk * NF;
    for (int f = tid; f < NF; f += 256) P[f] = accS[f];
}

// ---------------------------------------------------------------------------
// Deterministic reduction over the 128 partials per batch:
//   S[b,f] = sum_p P[b,p,f]
// ---------------------------------------------------------------------------
#define NPART (DD / CHB)   // 128
__global__ __launch_bounds__(256) void k_reduce()
{
    __shared__ float red[2][8][32];
    const int b    = blockIdx.y;
    const int lane = threadIdx.x & 31;
    const int cw   = threadIdx.x >> 5;
    const int f    = blockIdx.x * 32 + lane;

    float sr = 0.0f, si = 0.0f;
    if (f < NF) {
        for (int p = cw; p < NPART; p += 8) {
            float2 v = g_P[((size_t)b * NPART + p) * NF + f];
            sr += v.x; si += v.y;
        }
    }
    red[0][cw][lane] = sr;
    red[1][cw][lane] = si;
    __syncthreads();
    if (cw == 0 && f < NF) {
        float ar = 0.0f, ai = 0.0f;
#pragma unroll
        for (int w = 0; w < 8; w++) { ar += red[0][w][lane]; ai += red[1][w][lane]; }
        g_S[b * NF + f] = make_float2(ar, ai);
    }
}

// ---------------------------------------------------------------------------
// Per-batch inverse FFT -> mean_value, top-8 + softmax
// ---------------------------------------------------------------------------
__global__ __launch_bounds__(512) void k_ifft_topk()
{
    __shared__ __align__(16) float2 pool[2 * LL];
    float2* p0 = pool;
    float2* p1 = pool + LL;

    const int b = blockIdx.x;
    const int tid = threadIdx.x;
    const int nt = 512;

    for (int f = tid; f < LL; f += nt) {
        float2 v;
        if (f < NF) v = g_S[b * NF + f];
        else {
            float2 u = g_S[b * NF + (LL - f)];
            v = make_float2(u.x, -u.y);
        }
        p0[f] = v;
    }
    __syncthreads();

    float2* z = block_fft<-1>(p0, p1, tid, nt);   // z == p0

    // scratch lives in p1 (z occupies p0)
    float* meanArr = (float*)(pool + LL);
    float* redV    = meanArr + 3072;
    int*   redI    = (int*)(meanArr + 3584);

    const float scale = 1.0f / ((float)LL * (float)DD);
    for (int i = tid; i < LL; i += nt) meanArr[i] = z[i].x * scale;
    __syncthreads();

    float lw[TOPK];
    int   ld[TOPK];
    for (int k = 0; k < TOPK; k++) {
        float bv = -1e30f;
        int   bi = 0x7fffffff;
        for (int i = tid; i < LL; i += nt) {
            float v = meanArr[i];
            if (v > bv || (v == bv && i < bi)) { bv = v; bi = i; }
        }
        redV[tid] = bv; redI[tid] = bi;
        __syncthreads();
        for (int off = 256; off > 0; off >>= 1) {
            if (tid < off) {
                float v2 = redV[tid + off];
                int   i2 = redI[tid + off];
                if (v2 > redV[tid] || (v2 == redV[tid] && i2 < redI[tid])) {
                    redV[tid] = v2; redI[tid] = i2;
                }
            }
            __syncthreads();
        }
        if (tid == 0) {
            lw[k] = redV[0];
            ld[k] = redI[0];
            meanArr[redI[0]] = -1e30f;
        }
        __syncthreads();
    }

    if (tid == 0) {
        float mx = lw[0];
        for (int i = 1; i < TOPK; i++) mx = fmaxf(mx, lw[i]);
        float e[TOPK];
        float sum = 0.0f;
        for (int i = 0; i < TOPK; i++) { e[i] = expf(lw[i] - mx); sum += e[i]; }
        for (int i = 0; i < TOPK; i++) {
            g_w[b * TOPK + i] = e[i] / sum;
            g_d[b * TOPK + i] = ld[i];
        }
    }
}

// ---------------------------------------------------------------------------
// Time-delay aggregation over Y (Y already includes Wo and bo; sum w_i = 1):
//   Out[b][s][c] = sum_i w[b,i] * Y[b][(s+d_i)%L][c]
// ---------------------------------------------------------------------------
__global__ __launch_bounds__(256) void k_agg(float* __restrict__ Out)
{
    __shared__ float ws[TOPK];
    __shared__ int   ds[TOPK];
    const int s = blockIdx.x;
    const int b = blockIdx.y;
    const int tid = threadIdx.x;
    if (tid < TOPK) { ws[tid] = g_w[b * TOPK + tid]; ds[tid] = g_d[b * TOPK + tid]; }
    __syncthreads();

    const float* Yb = g_V + (size_t)b * LL * DD;
    const int c = tid * 4;
    float4 acc = make_float4(0.f, 0.f, 0.f, 0.f);
#pragma unroll
    for (int i = 0; i < TOPK; i++) {
        int j = s + ds[i];
        if (j >= LL) j -= LL;
        float4 v = *(const float4*)(Yb + (size_t)j * DD + c);
        float w = ws[i];
        acc.x += w * v.x; acc.y += w * v.y; acc.z += w * v.z; acc.w += w * v.w;
    }
    *(float4*)(Out + ((size_t)b * LL + s) * DD + c) = acc;
}

// ---------------------------------------------------------------------------
// kernel_launch
// ---------------------------------------------------------------------------
extern "C" void kernel_launch(void* const* d_in, const int* in_sizes, int n_in,
                              void* d_out, int out_size)
{
    const float* queries = (const float*)d_in[0];
    const float* keys    = (const float*)d_in[1];
    const float* values  = (const float*)d_in[2];
    const float* Wq = (const float*)d_in[3];
    const float* bq = (const float*)d_in[4];
    const float* Wk = (const float*)d_in[5];
    const float* bk = (const float*)d_in[6];
    const float* Wv = (const float*)d_in[7];
    const float* bv = (const float*)d_in[8];
    const float* Wo = (const float*)d_in[9];
    const float* bo = (const float*)d_in[10];
    float* Out = (float*)d_out;

    (void)in_sizes; (void)n_in; (void)out_size;

    const int dynG = NSTG * BUF_SZ;               // 98304 (> epilogue 67584)
    const int dynF = 2 * LL * 8 + NF * 8;         // 61448
    cudaFuncSetAttribute(k_gemm, cudaFuncAttributeMaxDynamicSharedMemorySize, dynG);
    cudaFuncSetAttribute(k_fft,  cudaFuncAttributeMaxDynamicSharedMemorySize, dynF);

    k_twiddle<<<(LL + 255) / 256, 256>>>();
    k_wconv<<<dim3(32, 32, 4), dim3(32, 8)>>>(Wq, Wk, Wv, Wo);

    const int nsplit = (int)((size_t)MTOT * DD / 1024);   // 24576 blocks
    k_asplit3<<<dim3(nsplit, 3), 256>>>((const float4*)queries,
                                        (const float4*)keys,
                                        (const float4*)values);

    // fused Q/K/V projection GEMMs (z selects operand set + output mode;
    // V-proj writes fp16(V) into region 0)
    k_gemm<<<dim3(DD / 128, MTOT / 128, 3), 256, dynG>>>(
        0, 0, bq, bk, bv, 0, 1);

    // Y = V @ Wo + bo (region 0) -> g_V
    k_gemm<<<dim3(DD / 128, MTOT / 128, 1), 256, dynG>>>(
        0, 3, bo, bo, bo, 3, 0);

    k_fft<<<BB * DD / CHB, 256, dynF>>>();
    k_reduce<<<dim3((NF + 31) / 32, BB), 256>>>();
    k_ifft_topk<<<BB, 512>>>();
    k_agg<<<dim3(LL, BB), 256>>>(Out);
}